// round 2
// baseline (speedup 1.0000x reference)
#include <cuda_runtime.h>

// Problem constants
#define Bdim 8
#define Nseq 2048
#define Edim 1024
#define Hh   16
#define Dd   64
#define Mrows (Bdim * Nseq)      // 16384

// GEMM tiling
#define BM 128
#define BN 128
#define BK 16
#define TM 8
#define TN 8
#define PAD 4

// Scratch (allocation-free rule: __device__ globals)
__device__ float g_qkv[(size_t)Mrows * 3 * Edim];   // 16384 x 3072  (192 MB)
__device__ float g_att[(size_t)Mrows * Edim];       // 16384 x 1024  (64 MB)

// ---------------------------------------------------------------------------
// NT GEMM: C[M,N] = A[M,K] (row-major) @ B[N,K]^T (row-major) + bias[N]
// 128x128 tile, BK=16, 256 threads, 8x8 per-thread, double-buffered smem.
// ---------------------------------------------------------------------------
__device__ __forceinline__ void load_tile(
    float (*As)[BM + PAD], float (*Bs)[BN + PAD],
    const float* __restrict__ Aptr, const float* __restrict__ Bptr,
    int K, int lrow, int lcol)
{
#pragma unroll
    for (int r = 0; r < 2; r++) {
        float4 va = *(const float4*)(Aptr + (size_t)r * 64 * K);
        As[lcol + 0][lrow + r * 64] = va.x;
        As[lcol + 1][lrow + r * 64] = va.y;
        As[lcol + 2][lrow + r * 64] = va.z;
        As[lcol + 3][lrow + r * 64] = va.w;
        float4 vb = *(const float4*)(Bptr + (size_t)r * 64 * K);
        Bs[lcol + 0][lrow + r * 64] = vb.x;
        Bs[lcol + 1][lrow + r * 64] = vb.y;
        Bs[lcol + 2][lrow + r * 64] = vb.z;
        Bs[lcol + 3][lrow + r * 64] = vb.w;
    }
}

__global__ __launch_bounds__(256, 2)
void gemm_nt_bias(const float* __restrict__ A, const float* __restrict__ B,
                  const float* __restrict__ bias, float* __restrict__ C,
                  int M, int N, int K)
{
    __shared__ float As[2][BK][BM + PAD];
    __shared__ float Bs[2][BK][BN + PAD];

    const int tid  = threadIdx.x;
    const int brow = blockIdx.y * BM;
    const int bcol = blockIdx.x * BN;
    const int tx   = tid & 15;          // 0..15 col group
    const int ty   = tid >> 4;          // 0..15 row group
    const int lrow = tid >> 2;          // 0..63
    const int lcol = (tid & 3) << 2;    // 0,4,8,12

    const float* Aptr = A + (size_t)(brow + lrow) * K + lcol;
    const float* Bptr = B + (size_t)(bcol + lrow) * K + lcol;

    float acc[TM][TN];
#pragma unroll
    for (int i = 0; i < TM; i++)
#pragma unroll
        for (int j = 0; j < TN; j++) acc[i][j] = 0.f;

    const int T = K / BK;

    load_tile(As[0], Bs[0], Aptr, Bptr, K, lrow, lcol);
    __syncthreads();

    int buf = 0;
    for (int t = 0; t < T; t++) {
        if (t + 1 < T) {
            load_tile(As[buf ^ 1], Bs[buf ^ 1],
                      Aptr + (size_t)(t + 1) * BK,
                      Bptr + (size_t)(t + 1) * BK, K, lrow, lcol);
        }
#pragma unroll
        for (int kk = 0; kk < BK; kk++) {
            float ar[TM], br[TN];
#pragma unroll
            for (int i = 0; i < TM; i++) ar[i] = As[buf][kk][ty * TM + i];
#pragma unroll
            for (int j = 0; j < TN; j++) br[j] = Bs[buf][kk][tx * TN + j];
#pragma unroll
            for (int i = 0; i < TM; i++)
#pragma unroll
                for (int j = 0; j < TN; j++)
                    acc[i][j] += ar[i] * br[j];
        }
        __syncthreads();
        buf ^= 1;
    }

    // epilogue: add bias, vectorized stores
#pragma unroll
    for (int i = 0; i < TM; i++) {
        const int row = brow + ty * TM + i;
#pragma unroll
        for (int j = 0; j < TN; j += 4) {
            const int col = bcol + tx * TN + j;
            float4 v;
            v.x = acc[i][j + 0] + bias[col + 0];
            v.y = acc[i][j + 1] + bias[col + 1];
            v.z = acc[i][j + 2] + bias[col + 2];
            v.w = acc[i][j + 3] + bias[col + 3];
            *(float4*)(&C[(size_t)row * N + col]) = v;
        }
    }
}

// ---------------------------------------------------------------------------
// Per-position "head attention" (replicates the einsum-label bug exactly).
// One block per (b, pos). qkv row layout: [q(16x64) | k(16x64) | v(16x64)].
// energy[i][j] = sum_d q[i,d]*k[j,d]; softmax over j (scale 1/32);
// out[i,d] = sum_l att[i,l]*v[l,d], written at raw [B,H,N,D] linear offset.
// ---------------------------------------------------------------------------
__global__ __launch_bounds__(256)
void attn_kernel(const float* __restrict__ qkv, float* __restrict__ out)
{
    __shared__ __align__(16) float s[3 * Edim];   // 3072 floats
    __shared__ float en[Hh][Hh + 1];
    __shared__ float rinv[Hh];

    const int bp  = blockIdx.x;          // b*2048 + pos
    const int b   = bp >> 11;
    const int pos = bp & 2047;
    const int tid = threadIdx.x;

    // load the whole qkv row (3072 floats) via float4
    {
        const float4* r4 = (const float4*)(qkv + (size_t)bp * 3072);
        float4* s4 = (float4*)s;
#pragma unroll
        for (int t = 0; t < 3; t++) s4[tid + t * 256] = r4[tid + t * 256];
    }
    __syncthreads();

    // energy: 256 threads, one per (i,j) head pair
    {
        const int i = tid >> 4;
        const int j = tid & 15;
        const float* q  = s + i * 64;
        const float* kp = s + 1024 + j * 64;
        float e = 0.f;
#pragma unroll
        for (int dd = 0; dd < 16; dd++) {
            const int d4 = ((dd + tid) & 15) * 4;   // per-thread rotation: kills bank conflicts
            float4 qv = *(const float4*)(q + d4);
            float4 kv = *(const float4*)(kp + d4);
            e += qv.x * kv.x + qv.y * kv.y + qv.z * kv.z + qv.w * kv.w;
        }
        en[i][j] = e * 0.03125f;   // 1/sqrt(1024)
    }
    __syncthreads();

    // softmax over j (16 rows handled by 16 threads)
    if (tid < Hh) {
        float m = -1e30f;
#pragma unroll
        for (int j = 0; j < Hh; j++) m = fmaxf(m, en[tid][j]);
        float sum = 0.f;
#pragma unroll
        for (int j = 0; j < Hh; j++) {
            const float v = __expf(en[tid][j] - m);
            en[tid][j] = v;
            sum += v;
        }
        rinv[tid] = 1.f / sum;
    }
    __syncthreads();

    // out[i][d] = (sum_l att[i][l] * v[l][d]) * rinv[i]
    // raw [B,H,N,D] layout: ((b*16+i)*2048 + pos)*64 + d
#pragma unroll
    for (int t0 = 0; t0 < 4; t0++) {
        const int t = tid + t0 * 256;
        const int i = t >> 6;
        const int d = t & 63;
        float o = 0.f;
#pragma unroll
        for (int l = 0; l < Hh; l++)
            o += en[i][l] * s[2048 + l * 64 + d];
        o *= rinv[i];
        out[((size_t)(b * Hh + i) * Nseq + pos) * Dd + d] = o;
    }
}

// ---------------------------------------------------------------------------
// launch
// ---------------------------------------------------------------------------
extern "C" void kernel_launch(void* const* d_in, const int* in_sizes, int n_in,
                              void* d_out, int out_size)
{
    const float* x    = (const float*)d_in[0];   // [8,2048,1024]
    const float* Wqkv = (const float*)d_in[1];   // [3072,1024]
    const float* bqkv = (const float*)d_in[2];   // [3072]
    const float* Wo   = (const float*)d_in[3];   // [1024,1024]
    const float* bo   = (const float*)d_in[4];   // [1024]
    float* out = (float*)d_out;                  // [8,2048,1024]

    float* qkv_buf;
    float* att_buf;
    cudaGetSymbolAddress((void**)&qkv_buf, g_qkv);
    cudaGetSymbolAddress((void**)&att_buf, g_att);

    // 1) qkv = x @ Wqkv^T + bqkv   [16384, 3072]
    {
        dim3 grid(3 * Edim / BN, Mrows / BM);
        gemm_nt_bias<<<grid, 256>>>(x, Wqkv, bqkv, qkv_buf, Mrows, 3 * Edim, Edim);
    }

    // 2) per-position head-attention -> raw [B,H,N,D] buffer == [16384,1024]
    attn_kernel<<<Mrows, 256>>>(qkv_buf, att_buf);

    // 3) out = Y @ Wo^T + bo   [16384, 1024]
    {
        dim3 grid(Edim / BN, Mrows / BM);
        gemm_nt_bias<<<grid, 256>>>(att_buf, Wo, bo, out, Mrows, Edim, Edim);
    }
}

// round 4
// speedup vs baseline: 2.2655x; 2.2655x over previous
#include <cuda_runtime.h>
#include <cuda_bf16.h>
#include <cstdint>

// Problem constants
#define Bdim 8
#define Nseq 2048
#define Edim 1024
#define Hh   16
#define Dd   64
#define Mrows (Bdim * Nseq)      // 16384

// ---------------------------------------------------------------------------
// Scratch (allocation-free rule: __device__ globals)
// ---------------------------------------------------------------------------
__device__ float          g_qkv[(size_t)Mrows * 3 * Edim];     // 192 MB fp32
__device__ __nv_bfloat16  g_xh [(size_t)Mrows * Edim];
__device__ __nv_bfloat16  g_xl [(size_t)Mrows * Edim];
__device__ __nv_bfloat16  g_ath[(size_t)Mrows * Edim];
__device__ __nv_bfloat16  g_atl[(size_t)Mrows * Edim];
__device__ __nv_bfloat16  g_wqh[(size_t)3 * Edim * Edim];
__device__ __nv_bfloat16  g_wql[(size_t)3 * Edim * Edim];
__device__ __nv_bfloat16  g_woh[(size_t)Edim * Edim];
__device__ __nv_bfloat16  g_wol[(size_t)Edim * Edim];

// ---------------------------------------------------------------------------
// Helpers (baseline-feature PTX only: cp.async, ldmatrix, mma.sync — sm_80+)
// ---------------------------------------------------------------------------
__device__ __forceinline__ uint32_t smem_u32(const void* p) {
    uint32_t a;
    asm("{ .reg .u64 t; cvta.to.shared.u64 t, %1; cvt.u32.u64 %0, t; }" : "=r"(a) : "l"(p));
    return a;
}
#define SWZ(x) ((x) ^ (((x) >> 3) & 0x70))

__device__ __forceinline__ void cp16(uint32_t dst, const void* src) {
    asm volatile("cp.async.cg.shared.global [%0], [%1], 16;" :: "r"(dst), "l"(src));
}
__device__ __forceinline__ void ldm4(uint32_t* r, uint32_t addr) {
    asm volatile("ldmatrix.sync.aligned.m8n8.x4.shared.b16 {%0,%1,%2,%3}, [%4];"
                 : "=r"(r[0]), "=r"(r[1]), "=r"(r[2]), "=r"(r[3]) : "r"(addr));
}
__device__ __forceinline__ void mma_bf16(float* c, const uint32_t* a, const uint32_t* b) {
    asm volatile(
        "mma.sync.aligned.m16n8k16.row.col.f32.bf16.bf16.f32 "
        "{%0,%1,%2,%3}, {%4,%5,%6,%7}, {%8,%9}, {%0,%1,%2,%3};"
        : "+f"(c[0]), "+f"(c[1]), "+f"(c[2]), "+f"(c[3])
        : "r"(a[0]), "r"(a[1]), "r"(a[2]), "r"(a[3]), "r"(b[0]), "r"(b[1]));
}

// ---------------------------------------------------------------------------
// bf16 hi/lo split
// ---------------------------------------------------------------------------
__device__ __forceinline__ void split1(float f, __nv_bfloat16& h, __nv_bfloat16& l) {
    h = __float2bfloat16(f);
    l = __float2bfloat16(f - __bfloat162float(h));
}

__global__ __launch_bounds__(256)
void split_kernel(const float4* __restrict__ src, uint2* __restrict__ hi,
                  uint2* __restrict__ lo, int n4)
{
    int i = blockIdx.x * 256 + threadIdx.x;
    if (i >= n4) return;
    float4 v = src[i];
    __nv_bfloat16 h0, l0, h1, l1, h2, l2, h3, l3;
    split1(v.x, h0, l0); split1(v.y, h1, l1);
    split1(v.z, h2, l2); split1(v.w, h3, l3);
    __nv_bfloat162 ph0 = __halves2bfloat162(h0, h1), ph1 = __halves2bfloat162(h2, h3);
    __nv_bfloat162 pl0 = __halves2bfloat162(l0, l1), pl1 = __halves2bfloat162(l2, l3);
    uint2 uh, ul;
    uh.x = *(uint32_t*)&ph0; uh.y = *(uint32_t*)&ph1;
    ul.x = *(uint32_t*)&pl0; ul.y = *(uint32_t*)&pl1;
    hi[i] = uh; lo[i] = ul;
}

// ---------------------------------------------------------------------------
// Split-bf16 NT GEMM via mma.sync (HMMA): C[M,N] = A @ B^T + bias, fp32 out.
// CTA tile 128x128, BK=64, 3-stage cp.async pipeline, 8 warps (2x4), 64x32/warp.
// C ~= Ah*Bh + Al*Bh + Ah*Bl  (drops Al*Bl ~ 2^-18 relative)
// ---------------------------------------------------------------------------
#define STAGES 3
#define STG_BYTES 65536   // Ah|Al|Bh|Bl, 16KB each
#define GSMEM (STAGES * STG_BYTES + 1024)

__global__ __launch_bounds__(256, 1)
void gemm_mma(const __nv_bfloat16* __restrict__ Ah, const __nv_bfloat16* __restrict__ Al,
              const __nv_bfloat16* __restrict__ Bh, const __nv_bfloat16* __restrict__ Bl,
              const float* __restrict__ bias, float* __restrict__ C, int N)
{
    extern __shared__ char smem_raw[];
    const uint32_t sb = (smem_u32(smem_raw) + 1023) & ~1023u;   // 1KB-align for swizzle
    const int tid  = threadIdx.x;
    const int lane = tid & 31;
    const int wid  = tid >> 5;
    const int wm   = wid >> 2;          // 0..1  (M)
    const int wn   = wid & 3;           // 0..3  (N)
    const int brow = blockIdx.y * 128;
    const int bcol = blockIdx.x * 128;

    float acc[4][4][4];
#pragma unroll
    for (int i = 0; i < 4; i++)
#pragma unroll
        for (int j = 0; j < 4; j++)
#pragma unroll
            for (int k = 0; k < 4; k++) acc[i][j][k] = 0.f;

    // ---- stage loader: 4 tiles x 128 rows x 8 chunks(16B) = 4096 chunks ----
    auto load_stage = [&](int buf, int ks) {
#pragma unroll
        for (int i = 0; i < 16; i++) {
            const int cid  = tid + i * 256;
            const int tile = cid >> 10;
            const int r    = (cid >> 3) & 127;
            const int c    = cid & 7;
            const __nv_bfloat16* base =
                (tile == 0) ? Ah : (tile == 1) ? Al : (tile == 2) ? Bh : Bl;
            const int row0 = ((tile < 2) ? brow : bcol) + r;
            cp16(sb + buf * STG_BYTES + tile * 16384 + SWZ(r * 128 + c * 16),
                 base + (size_t)row0 * Edim + ks + c * 8);
        }
        asm volatile("cp.async.commit_group;");
    };

    int fetch = 0;
    for (; fetch < STAGES - 1; ++fetch) load_stage(fetch, fetch * 64);

    const int lrow = lane & 15;
    const int lkb  = (lane >> 4) * 16;

    for (int s = 0; s < 16; ++s) {
        if (fetch < 16) { load_stage(fetch % STAGES, fetch * 64); ++fetch; }
        else            { asm volatile("cp.async.commit_group;"); }
        asm volatile("cp.async.wait_group 2;");
        __syncthreads();

        const uint32_t stg = sb + (s % STAGES) * STG_BYTES;
#pragma unroll
        for (int kk = 0; kk < 4; kk++) {
            uint32_t a[4][4], b0[2][4], b1[2][4];
            // Ah fragments (4 m-tiles of 16)
#pragma unroll
            for (int mt = 0; mt < 4; mt++)
                ldm4(a[mt], stg + SWZ((wm * 64 + mt * 16 + lrow) * 128 + kk * 32 + lkb));
            // Bh fragments (2 x 16 n-rows)
#pragma unroll
            for (int p = 0; p < 2; p++)
                ldm4(b0[p], stg + 32768 + SWZ((wn * 32 + p * 16 + lrow) * 128 + kk * 32 + lkb));
            // Bl fragments
#pragma unroll
            for (int p = 0; p < 2; p++)
                ldm4(b1[p], stg + 49152 + SWZ((wn * 32 + p * 16 + lrow) * 128 + kk * 32 + lkb));

            // Ah*Bh + Ah*Bl
#pragma unroll
            for (int mt = 0; mt < 4; mt++)
#pragma unroll
                for (int nt = 0; nt < 4; nt++) {
                    uint32_t bh[2] = { b0[nt >> 1][nt & 1], b0[nt >> 1][(nt & 1) + 2] };
                    mma_bf16(acc[mt][nt], a[mt], bh);
                    uint32_t bl[2] = { b1[nt >> 1][nt & 1], b1[nt >> 1][(nt & 1) + 2] };
                    mma_bf16(acc[mt][nt], a[mt], bl);
                }
            // Al fragments, then Al*Bh
#pragma unroll
            for (int mt = 0; mt < 4; mt++)
                ldm4(a[mt], stg + 16384 + SWZ((wm * 64 + mt * 16 + lrow) * 128 + kk * 32 + lkb));
#pragma unroll
            for (int mt = 0; mt < 4; mt++)
#pragma unroll
                for (int nt = 0; nt < 4; nt++) {
                    uint32_t bh[2] = { b0[nt >> 1][nt & 1], b0[nt >> 1][(nt & 1) + 2] };
                    mma_bf16(acc[mt][nt], a[mt], bh);
                }
        }
        __syncthreads();
    }

    // ---- epilogue: bias add, float2 stores ----
    const int g  = lane >> 2;
    const int q2 = (lane & 3) * 2;
#pragma unroll
    for (int mt = 0; mt < 4; mt++) {
#pragma unroll
        for (int h = 0; h < 2; h++) {
            const int row = brow + wm * 64 + mt * 16 + g + h * 8;
#pragma unroll
            for (int nt = 0; nt < 4; nt++) {
                const int col = bcol + wn * 32 + nt * 8 + q2;
                float2 v;
                v.x = acc[mt][nt][2 * h + 0] + __ldg(bias + col + 0);
                v.y = acc[mt][nt][2 * h + 1] + __ldg(bias + col + 1);
                *(float2*)(C + (size_t)row * N + col) = v;
            }
        }
    }
}

// ---------------------------------------------------------------------------
// Per-position "head attention" (einsum-label bug replicated exactly).
// Emits bf16 hi/lo split of the output directly (feeds GEMM2).
// ---------------------------------------------------------------------------
__global__ __launch_bounds__(256)
void attn_kernel(const float* __restrict__ qkv,
                 __nv_bfloat16* __restrict__ oh, __nv_bfloat16* __restrict__ ol)
{
    __shared__ __align__(16) float s[3 * Edim];
    __shared__ float en[Hh][Hh + 1];
    __shared__ float rinv[Hh];

    const int bp  = blockIdx.x;
    const int b   = bp >> 11;
    const int pos = bp & 2047;
    const int tid = threadIdx.x;

    {
        const float4* r4 = (const float4*)(qkv + (size_t)bp * 3072);
        float4* s4 = (float4*)s;
#pragma unroll
        for (int t = 0; t < 3; t++) s4[tid + t * 256] = r4[tid + t * 256];
    }
    __syncthreads();

    {
        const int i = tid >> 4;
        const int j = tid & 15;
        const float* q  = s + i * 64;
        const float* kp = s + 1024 + j * 64;
        float e = 0.f;
#pragma unroll
        for (int dd = 0; dd < 16; dd++) {
            const int d4 = ((dd + tid) & 15) * 4;
            float4 qv = *(const float4*)(q + d4);
            float4 kv = *(const float4*)(kp + d4);
            e += qv.x * kv.x + qv.y * kv.y + qv.z * kv.z + qv.w * kv.w;
        }
        en[i][j] = e * 0.03125f;   // 1/sqrt(1024)
    }
    __syncthreads();

    if (tid < Hh) {
        float m = -1e30f;
#pragma unroll
        for (int j = 0; j < Hh; j++) m = fmaxf(m, en[tid][j]);
        float sum = 0.f;
#pragma unroll
        for (int j = 0; j < Hh; j++) {
            const float v = __expf(en[tid][j] - m);
            en[tid][j] = v;
            sum += v;
        }
        rinv[tid] = 1.f / sum;
    }
    __syncthreads();

#pragma unroll
    for (int t0 = 0; t0 < 4; t0++) {
        const int t = tid + t0 * 256;
        const int i = t >> 6;
        const int d = t & 63;
        float o = 0.f;
#pragma unroll
        for (int l = 0; l < Hh; l++)
            o += en[i][l] * s[2048 + l * 64 + d];
        o *= rinv[i];
        const size_t idx = ((size_t)(b * Hh + i) * Nseq + pos) * Dd + d;
        __nv_bfloat16 h, lo_;
        split1(o, h, lo_);
        oh[idx] = h;
        ol[idx] = lo_;
    }
}

// ---------------------------------------------------------------------------
// launch
// ---------------------------------------------------------------------------
extern "C" void kernel_launch(void* const* d_in, const int* in_sizes, int n_in,
                              void* d_out, int out_size)
{
    const float* x    = (const float*)d_in[0];   // [16384,1024]
    const float* Wqkv = (const float*)d_in[1];   // [3072,1024]
    const float* bqkv = (const float*)d_in[2];
    const float* Wo   = (const float*)d_in[3];   // [1024,1024]
    const float* bo   = (const float*)d_in[4];
    float* out = (float*)d_out;

    float* qkv_buf;
    __nv_bfloat16 *xh, *xl, *ath, *atl, *wqh, *wql, *woh, *wol;
    cudaGetSymbolAddress((void**)&qkv_buf, g_qkv);
    cudaGetSymbolAddress((void**)&xh,  g_xh);
    cudaGetSymbolAddress((void**)&xl,  g_xl);
    cudaGetSymbolAddress((void**)&ath, g_ath);
    cudaGetSymbolAddress((void**)&atl, g_atl);
    cudaGetSymbolAddress((void**)&wqh, g_wqh);
    cudaGetSymbolAddress((void**)&wql, g_wql);
    cudaGetSymbolAddress((void**)&woh, g_woh);
    cudaGetSymbolAddress((void**)&wol, g_wol);

    cudaFuncSetAttribute(gemm_mma, cudaFuncAttributeMaxDynamicSharedMemorySize, GSMEM);

    // 0) bf16 hi/lo splits of x, Wqkv, Wo
    {
        int n4 = Mrows * Edim / 4;
        split_kernel<<<(n4 + 255) / 256, 256>>>((const float4*)x, (uint2*)xh, (uint2*)xl, n4);
        n4 = 3 * Edim * Edim / 4;
        split_kernel<<<(n4 + 255) / 256, 256>>>((const float4*)Wqkv, (uint2*)wqh, (uint2*)wql, n4);
        n4 = Edim * Edim / 4;
        split_kernel<<<(n4 + 255) / 256, 256>>>((const float4*)Wo, (uint2*)woh, (uint2*)wol, n4);
    }

    // 1) qkv = x @ Wqkv^T + bqkv   [16384, 3072]
    {
        dim3 grid(3 * Edim / 128, Mrows / 128);
        gemm_mma<<<grid, 256, GSMEM>>>(xh, xl, wqh, wql, bqkv, qkv_buf, 3 * Edim);
    }

    // 2) per-position head-attention -> bf16 hi/lo in raw [B,H,N,D] layout
    attn_kernel<<<Mrows, 256>>>(qkv_buf, ath, atl);

    // 3) out = Y @ Wo^T + bo   [16384, 1024]
    {
        dim3 grid(Edim / 128, Mrows / 128);
        gemm_mma<<<grid, 256, GSMEM>>>(ath, atl, woh, wol, bo, out, Edim);
    }
}

// round 6
// speedup vs baseline: 2.3784x; 1.0498x over previous
#include <cuda_runtime.h>
#include <cuda_bf16.h>
#include <cstdint>

// Problem constants
#define Bdim 8
#define Nseq 2048
#define Edim 1024
#define Hh   16
#define Dd   64
#define Mrows (Bdim * Nseq)      // 16384

// ---------------------------------------------------------------------------
// Scratch (allocation-free rule: __device__ globals)
// ---------------------------------------------------------------------------
__device__ float          g_qkv[(size_t)Mrows * 3 * Edim];     // 192 MB fp32
__device__ __nv_bfloat16  g_xh [(size_t)Mrows * Edim];
__device__ __nv_bfloat16  g_xl [(size_t)Mrows * Edim];
__device__ __nv_bfloat16  g_ath[(size_t)Mrows * Edim];
__device__ __nv_bfloat16  g_atl[(size_t)Mrows * Edim];
__device__ __nv_bfloat16  g_wqh[(size_t)3 * Edim * Edim];
__device__ __nv_bfloat16  g_wql[(size_t)3 * Edim * Edim];
__device__ __nv_bfloat16  g_woh[(size_t)Edim * Edim];
__device__ __nv_bfloat16  g_wol[(size_t)Edim * Edim];

// ---------------------------------------------------------------------------
// Helpers (baseline-feature PTX only: cp.async, ldmatrix, mma.sync — sm_80+)
// ---------------------------------------------------------------------------
__device__ __forceinline__ uint32_t smem_u32(const void* p) {
    uint32_t a;
    asm("{ .reg .u64 t; cvta.to.shared.u64 t, %1; cvt.u32.u64 %0, t; }" : "=r"(a) : "l"(p));
    return a;
}
#define SWZ(x) ((x) ^ (((x) >> 3) & 0x70))

__device__ __forceinline__ void cp16(uint32_t dst, const void* src) {
    asm volatile("cp.async.cg.shared.global [%0], [%1], 16;" :: "r"(dst), "l"(src));
}
__device__ __forceinline__ void ldm4(uint32_t* r, uint32_t addr) {
    asm volatile("ldmatrix.sync.aligned.m8n8.x4.shared.b16 {%0,%1,%2,%3}, [%4];"
                 : "=r"(r[0]), "=r"(r[1]), "=r"(r[2]), "=r"(r[3]) : "r"(addr));
}
__device__ __forceinline__ void mma_bf16(float* c, const uint32_t* a, uint32_t b0, uint32_t b1) {
    asm volatile(
        "mma.sync.aligned.m16n8k16.row.col.f32.bf16.bf16.f32 "
        "{%0,%1,%2,%3}, {%4,%5,%6,%7}, {%8,%9}, {%0,%1,%2,%3};"
        : "+f"(c[0]), "+f"(c[1]), "+f"(c[2]), "+f"(c[3])
        : "r"(a[0]), "r"(a[1]), "r"(a[2]), "r"(a[3]), "r"(b0), "r"(b1));
}

// ---------------------------------------------------------------------------
// bf16 hi/lo split
// ---------------------------------------------------------------------------
__device__ __forceinline__ void split1(float f, __nv_bfloat16& h, __nv_bfloat16& l) {
    h = __float2bfloat16(f);
    l = __float2bfloat16(f - __bfloat162float(h));
}

__global__ __launch_bounds__(256)
void split_kernel(const float4* __restrict__ src, uint2* __restrict__ hi,
                  uint2* __restrict__ lo, int n4)
{
    int i = blockIdx.x * 256 + threadIdx.x;
    if (i >= n4) return;
    float4 v = src[i];
    __nv_bfloat16 h0, l0, h1, l1, h2, l2, h3, l3;
    split1(v.x, h0, l0); split1(v.y, h1, l1);
    split1(v.z, h2, l2); split1(v.w, h3, l3);
    __nv_bfloat162 ph0 = __halves2bfloat162(h0, h1), ph1 = __halves2bfloat162(h2, h3);
    __nv_bfloat162 pl0 = __halves2bfloat162(l0, l1), pl1 = __halves2bfloat162(l2, l3);
    uint2 uh, ul;
    uh.x = *(uint32_t*)&ph0; uh.y = *(uint32_t*)&ph1;
    ul.x = *(uint32_t*)&pl0; ul.y = *(uint32_t*)&pl1;
    hi[i] = uh; lo[i] = ul;
}

// ---------------------------------------------------------------------------
// Split-bf16 NT GEMM via mma.sync (HMMA): C[M,N] = A @ B^T + bias, fp32 out.
// CTA tile 128x128, BK=64, 3-stage cp.async pipeline, 512 threads (16 warps,
// 4x4 grid, 32x32 per warp). C ~= Ah*Bh + Al*Bh + Ah*Bl.
// NOTE: kk advance inside a swizzled address is XOR (bits 5-6 are inside the
// swizzle field); mt/p advance (bit 11) is plain add.
// ---------------------------------------------------------------------------
#define STAGES 3
#define STG_BYTES 65536   // Ah|Al|Bh|Bl, 16KB each
#define GSMEM (STAGES * STG_BYTES + 1024)
#define NTHREADS 512

__global__ __launch_bounds__(NTHREADS, 1)
void gemm_mma(const __nv_bfloat16* __restrict__ Ah, const __nv_bfloat16* __restrict__ Al,
              const __nv_bfloat16* __restrict__ Bh, const __nv_bfloat16* __restrict__ Bl,
              const float* __restrict__ bias, float* __restrict__ C, int N)
{
    extern __shared__ char smem_raw[];
    const uint32_t sb = (smem_u32(smem_raw) + 1023) & ~1023u;
    const int tid  = threadIdx.x;
    const int lane = tid & 31;
    const int wid  = tid >> 5;
    const int wm   = wid >> 2;          // 0..3  (M)
    const int wn   = wid & 3;           // 0..3  (N)
    const int brow = blockIdx.y * 128;
    const int bcol = blockIdx.x * 128;

    float acc[2][4][4];
#pragma unroll
    for (int i = 0; i < 2; i++)
#pragma unroll
        for (int j = 0; j < 4; j++)
#pragma unroll
            for (int k = 0; k < 4; k++) acc[i][j][k] = 0.f;

    // Hoisted swizzled ldmatrix base offsets. Pre-swizzle bits 5-6 are zero
    // (lkb is bit 4, rows are bits >=7), so the kk*32 advance applies as XOR
    // on the swizzled address; mt*2048 / p*2048 apply as adds (no carries:
    // lrow*128 + 2048 < 4096).
    const int  lrow   = lane & 15;
    const int  lkb    = (lane >> 4) * 16;
    const uint32_t a_base = SWZ((wm * 32 + lrow) * 128 + lkb);
    const uint32_t b_base = SWZ((wn * 32 + lrow) * 128 + lkb);

    // ---- stage loader: 4 tiles x 128 rows x 8 chunks(16B) = 4096 chunks ----
    auto load_stage = [&](int buf, int ks) {
#pragma unroll
        for (int i = 0; i < 8; i++) {
            const int cid  = tid + i * NTHREADS;
            const int tile = cid >> 10;
            const int r    = (cid >> 3) & 127;
            const int c    = cid & 7;
            const __nv_bfloat16* base =
                (tile == 0) ? Ah : (tile == 1) ? Al : (tile == 2) ? Bh : Bl;
            const int row0 = ((tile < 2) ? brow : bcol) + r;
            cp16(sb + buf * STG_BYTES + tile * 16384 + SWZ(r * 128 + c * 16),
                 base + (size_t)row0 * Edim + ks + c * 8);
        }
        asm volatile("cp.async.commit_group;");
    };

    load_stage(0, 0);
    load_stage(1, 64);
    int fetch = 2;

    for (int s = 0; s < 16; ++s) {
        asm volatile("cp.async.wait_group 1;");
        __syncthreads();
        if (fetch < 16) { load_stage(fetch % STAGES, fetch * 64); ++fetch; }
        else            { asm volatile("cp.async.commit_group;"); }

        const uint32_t stg = sb + (s % STAGES) * STG_BYTES;
#pragma unroll
        for (int kk = 0; kk < 4; kk++) {
            const uint32_t kx = kk * 32;
            uint32_t ah[2][4], al[2][4], bh[2][4], bl[2][4];
#pragma unroll
            for (int mt = 0; mt < 2; mt++) {
                ldm4(ah[mt], stg +         ((a_base + mt * 2048) ^ kx));
                ldm4(al[mt], stg + 16384 + ((a_base + mt * 2048) ^ kx));
            }
#pragma unroll
            for (int p = 0; p < 2; p++) {
                ldm4(bh[p], stg + 32768 + ((b_base + p * 2048) ^ kx));
                ldm4(bl[p], stg + 49152 + ((b_base + p * 2048) ^ kx));
            }
#pragma unroll
            for (int mt = 0; mt < 2; mt++)
#pragma unroll
                for (int nt = 0; nt < 4; nt++) {
                    const int p = nt >> 1, q = nt & 1;
                    mma_bf16(acc[mt][nt], ah[mt], bh[p][q], bh[p][q + 2]);
                    mma_bf16(acc[mt][nt], ah[mt], bl[p][q], bl[p][q + 2]);
                    mma_bf16(acc[mt][nt], al[mt], bh[p][q], bh[p][q + 2]);
                }
        }
    }

    // ---- epilogue: bias add, float2 stores ----
    const int g  = lane >> 2;
    const int q2 = (lane & 3) * 2;
#pragma unroll
    for (int mt = 0; mt < 2; mt++) {
#pragma unroll
        for (int h = 0; h < 2; h++) {
            const int row = brow + wm * 32 + mt * 16 + g + h * 8;
#pragma unroll
            for (int nt = 0; nt < 4; nt++) {
                const int col = bcol + wn * 32 + nt * 8 + q2;
                float2 v;
                v.x = acc[mt][nt][2 * h + 0] + __ldg(bias + col + 0);
                v.y = acc[mt][nt][2 * h + 1] + __ldg(bias + col + 1);
                *(float2*)(C + (size_t)row * N + col) = v;
            }
        }
    }
}

// ---------------------------------------------------------------------------
// Per-position "head attention" (einsum-label bug replicated exactly).
// Emits bf16 hi/lo split of the output directly (feeds GEMM2).
// ---------------------------------------------------------------------------
__global__ __launch_bounds__(256)
void attn_kernel(const float* __restrict__ qkv,
                 __nv_bfloat16* __restrict__ oh, __nv_bfloat16* __restrict__ ol)
{
    __shared__ __align__(16) float s[3 * Edim];
    __shared__ float en[Hh][Hh + 1];
    __shared__ float rinv[Hh];

    const int bp  = blockIdx.x;
    const int b   = bp >> 11;
    const int pos = bp & 2047;
    const int tid = threadIdx.x;

    {
        const float4* r4 = (const float4*)(qkv + (size_t)bp * 3072);
        float4* s4 = (float4*)s;
#pragma unroll
        for (int t = 0; t < 3; t++) s4[tid + t * 256] = r4[tid + t * 256];
    }
    __syncthreads();

    {
        const int i = tid >> 4;
        const int j = tid & 15;
        const float* q  = s + i * 64;
        const float* kp = s + 1024 + j * 64;
        float e = 0.f;
#pragma unroll
        for (int dd = 0; dd < 16; dd++) {
            const int d4 = ((dd + tid) & 15) * 4;
            float4 qv = *(const float4*)(q + d4);
            float4 kv = *(const float4*)(kp + d4);
            e += qv.x * kv.x + qv.y * kv.y + qv.z * kv.z + qv.w * kv.w;
        }
        en[i][j] = e * 0.03125f;   // 1/sqrt(1024)
    }
    __syncthreads();

    if (tid < Hh) {
        float m = -1e30f;
#pragma unroll
        for (int j = 0; j < Hh; j++) m = fmaxf(m, en[tid][j]);
        float sum = 0.f;
#pragma unroll
        for (int j = 0; j < Hh; j++) {
            const float v = __expf(en[tid][j] - m);
            en[tid][j] = v;
            sum += v;
        }
        rinv[tid] = 1.f / sum;
    }
    __syncthreads();

#pragma unroll
    for (int t0 = 0; t0 < 4; t0++) {
        const int t = tid + t0 * 256;
        const int i = t >> 6;
        const int d = t & 63;
        float o = 0.f;
#pragma unroll
        for (int l = 0; l < Hh; l++)
            o += en[i][l] * s[2048 + l * 64 + d];
        o *= rinv[i];
        const size_t idx = ((size_t)(b * Hh + i) * Nseq + pos) * Dd + d;
        __nv_bfloat16 h, lo_;
        split1(o, h, lo_);
        oh[idx] = h;
        ol[idx] = lo_;
    }
}

// ---------------------------------------------------------------------------
// launch
// ---------------------------------------------------------------------------
extern "C" void kernel_launch(void* const* d_in, const int* in_sizes, int n_in,
                              void* d_out, int out_size)
{
    const float* x    = (const float*)d_in[0];   // [16384,1024]
    const float* Wqkv = (const float*)d_in[1];   // [3072,1024]
    const float* bqkv = (const float*)d_in[2];
    const float* Wo   = (const float*)d_in[3];   // [1024,1024]
    const float* bo   = (const float*)d_in[4];
    float* out = (float*)d_out;

    float* qkv_buf;
    __nv_bfloat16 *xh, *xl, *ath, *atl, *wqh, *wql, *woh, *wol;
    cudaGetSymbolAddress((void**)&qkv_buf, g_qkv);
    cudaGetSymbolAddress((void**)&xh,  g_xh);
    cudaGetSymbolAddress((void**)&xl,  g_xl);
    cudaGetSymbolAddress((void**)&ath, g_ath);
    cudaGetSymbolAddress((void**)&atl, g_atl);
    cudaGetSymbolAddress((void**)&wqh, g_wqh);
    cudaGetSymbolAddress((void**)&wql, g_wql);
    cudaGetSymbolAddress((void**)&woh, g_woh);
    cudaGetSymbolAddress((void**)&wol, g_wol);

    cudaFuncSetAttribute(gemm_mma, cudaFuncAttributeMaxDynamicSharedMemorySize, GSMEM);

    // 0) bf16 hi/lo splits of x, Wqkv, Wo
    {
        int n4 = Mrows * Edim / 4;
        split_kernel<<<(n4 + 255) / 256, 256>>>((const float4*)x, (uint2*)xh, (uint2*)xl, n4);
        n4 = 3 * Edim * Edim / 4;
        split_kernel<<<(n4 + 255) / 256, 256>>>((const float4*)Wqkv, (uint2*)wqh, (uint2*)wql, n4);
        n4 = Edim * Edim / 4;
        split_kernel<<<(n4 + 255) / 256, 256>>>((const float4*)Wo, (uint2*)woh, (uint2*)wol, n4);
    }

    // 1) qkv = x @ Wqkv^T + bqkv   [16384, 3072]
    {
        dim3 grid(3 * Edim / 128, Mrows / 128);
        gemm_mma<<<grid, NTHREADS, GSMEM>>>(xh, xl, wqh, wql, bqkv, qkv_buf, 3 * Edim);
    }

    // 2) per-position head-attention -> bf16 hi/lo in raw [B,H,N,D] layout
    attn_kernel<<<Mrows, 256>>>(qkv_buf, ath, atl);

    // 3) out = Y @ Wo^T + bo   [16384, 1024]
    {
        dim3 grid(Edim / 128, Mrows / 128);
        gemm_mma<<<grid, NTHREADS, GSMEM>>>(ath, atl, woh, wol, bo, out, Edim);
    }
}

// round 7
// speedup vs baseline: 3.3638x; 1.4143x over previous
#include <cuda_runtime.h>
#include <cuda_fp16.h>
#include <cstdint>

// Problem constants
#define Bdim 8
#define Nseq 2048
#define Edim 1024
#define Hh   16
#define Dd   64
#define Mrows (Bdim * Nseq)      // 16384

// ---------------------------------------------------------------------------
// Scratch (allocation-free rule: __device__ globals)
// ---------------------------------------------------------------------------
__device__ float   g_qkv[(size_t)Mrows * 3 * Edim];   // 192 MB fp32
__device__ __half  g_xh [(size_t)Mrows * Edim];       // x as fp16
__device__ __half  g_ath[(size_t)Mrows * Edim];       // attn out as fp16
__device__ __half  g_wqh[(size_t)3 * Edim * Edim];
__device__ __half  g_wql[(size_t)3 * Edim * Edim];
__device__ __half  g_woh[(size_t)Edim * Edim];
__device__ __half  g_wol[(size_t)Edim * Edim];

// ---------------------------------------------------------------------------
// Helpers (baseline-feature PTX only: cp.async, ldmatrix, mma.sync — sm_80+)
// ---------------------------------------------------------------------------
__device__ __forceinline__ uint32_t smem_u32(const void* p) {
    uint32_t a;
    asm("{ .reg .u64 t; cvta.to.shared.u64 t, %1; cvt.u32.u64 %0, t; }" : "=r"(a) : "l"(p));
    return a;
}
#define SWZ(x) ((x) ^ (((x) >> 3) & 0x70))

__device__ __forceinline__ void cp16(uint32_t dst, const void* src) {
    asm volatile("cp.async.cg.shared.global [%0], [%1], 16;" :: "r"(dst), "l"(src));
}
__device__ __forceinline__ void ldm4(uint32_t* r, uint32_t addr) {
    asm volatile("ldmatrix.sync.aligned.m8n8.x4.shared.b16 {%0,%1,%2,%3}, [%4];"
                 : "=r"(r[0]), "=r"(r[1]), "=r"(r[2]), "=r"(r[3]) : "r"(addr));
}
__device__ __forceinline__ void mma_f16(float* c, const uint32_t* a, uint32_t b0, uint32_t b1) {
    asm volatile(
        "mma.sync.aligned.m16n8k16.row.col.f32.f16.f16.f32 "
        "{%0,%1,%2,%3}, {%4,%5,%6,%7}, {%8,%9}, {%0,%1,%2,%3};"
        : "+f"(c[0]), "+f"(c[1]), "+f"(c[2]), "+f"(c[3])
        : "r"(a[0]), "r"(a[1]), "r"(a[2]), "r"(a[3]), "r"(b0), "r"(b1));
}

// ---------------------------------------------------------------------------
// fp16 conversion / hi-lo split kernels
// ---------------------------------------------------------------------------
__global__ __launch_bounds__(256)
void tohalf_kernel(const float4* __restrict__ src, uint2* __restrict__ dst, int n4)
{
    int i = blockIdx.x * 256 + threadIdx.x;
    if (i >= n4) return;
    float4 v = src[i];
    __half2 p0 = __floats2half2_rn(v.x, v.y);
    __half2 p1 = __floats2half2_rn(v.z, v.w);
    uint2 u;
    u.x = *(uint32_t*)&p0; u.y = *(uint32_t*)&p1;
    dst[i] = u;
}

__device__ __forceinline__ void split1h(float f, __half& h, __half& l) {
    h = __float2half_rn(f);
    l = __float2half_rn(f - __half2float(h));
}

__global__ __launch_bounds__(256)
void split16_kernel(const float4* __restrict__ src, uint2* __restrict__ hi,
                    uint2* __restrict__ lo, int n4)
{
    int i = blockIdx.x * 256 + threadIdx.x;
    if (i >= n4) return;
    float4 v = src[i];
    __half h0, l0, h1, l1, h2, l2, h3, l3;
    split1h(v.x, h0, l0); split1h(v.y, h1, l1);
    split1h(v.z, h2, l2); split1h(v.w, h3, l3);
    __half2 ph0 = __halves2half2(h0, h1), ph1 = __halves2half2(h2, h3);
    __half2 pl0 = __halves2half2(l0, l1), pl1 = __halves2half2(l2, l3);
    uint2 uh, ul;
    uh.x = *(uint32_t*)&ph0; uh.y = *(uint32_t*)&ph1;
    ul.x = *(uint32_t*)&pl0; ul.y = *(uint32_t*)&pl1;
    hi[i] = uh; lo[i] = ul;
}

// ---------------------------------------------------------------------------
// Split-fp16 NT GEMM via mma.sync: C[M,N] = A @ (Bh+Bl)^T + bias, fp32 out.
// A is fp16-rounded (error 2^-12); B split hi/lo fp16 (error 2^-22).
// CTA tile 128x128, BK=64, 3-stage cp.async pipeline, 512 threads (16 warps,
// 4x4 grid, 32x32 per warp). 2 products: Ah*Bh + Ah*Bl.
// kk advance inside a swizzled address is XOR (bits 5-6 inside swizzle field).
// ---------------------------------------------------------------------------
#define STAGES 3
#define STG_BYTES 49152   // A|Bh|Bl, 16KB each
#define GSMEM (STAGES * STG_BYTES + 1024)
#define NTHREADS 512

__global__ __launch_bounds__(NTHREADS, 1)
void gemm_mma(const __half* __restrict__ A, const __half* __restrict__ Bh,
              const __half* __restrict__ Bl, const float* __restrict__ bias,
              float* __restrict__ C, int N)
{
    extern __shared__ char smem_raw[];
    const uint32_t sb = (smem_u32(smem_raw) + 1023) & ~1023u;
    const int tid  = threadIdx.x;
    const int lane = tid & 31;
    const int wid  = tid >> 5;
    const int wm   = wid >> 2;          // 0..3  (M)
    const int wn   = wid & 3;           // 0..3  (N)
    const int brow = blockIdx.y * 128;
    const int bcol = blockIdx.x * 128;

    float acc[2][4][4];
#pragma unroll
    for (int i = 0; i < 2; i++)
#pragma unroll
        for (int j = 0; j < 4; j++)
#pragma unroll
            for (int k = 0; k < 4; k++) acc[i][j][k] = 0.f;

    const int  lrow   = lane & 15;
    const int  lkb    = (lane >> 4) * 16;
    const uint32_t a_base = SWZ((wm * 32 + lrow) * 128 + lkb);
    const uint32_t b_base = SWZ((wn * 32 + lrow) * 128 + lkb);

    // ---- stage loader: 3 tiles x 128 rows x 8 chunks(16B) = 3072 chunks ----
    auto load_stage = [&](int buf, int ks) {
#pragma unroll
        for (int i = 0; i < 6; i++) {
            const int cid  = tid + i * NTHREADS;
            const int tile = cid >> 10;          // 0=A 1=Bh 2=Bl
            const int r    = (cid >> 3) & 127;
            const int c    = cid & 7;
            const __half* base = (tile == 0) ? A : (tile == 1) ? Bh : Bl;
            const int row0 = ((tile == 0) ? brow : bcol) + r;
            cp16(sb + buf * STG_BYTES + tile * 16384 + SWZ(r * 128 + c * 16),
                 base + (size_t)row0 * Edim + ks + c * 8);
        }
        asm volatile("cp.async.commit_group;");
    };

    load_stage(0, 0);
    load_stage(1, 64);
    int fetch = 2;

    for (int s = 0; s < 16; ++s) {
        asm volatile("cp.async.wait_group 1;");
        __syncthreads();
        if (fetch < 16) { load_stage(fetch % STAGES, fetch * 64); ++fetch; }
        else            { asm volatile("cp.async.commit_group;"); }

        const uint32_t stg = sb + (s % STAGES) * STG_BYTES;
#pragma unroll
        for (int kk = 0; kk < 4; kk++) {
            const uint32_t kx = kk * 32;
            uint32_t a[2][4], bh[2][4], bl[2][4];
#pragma unroll
            for (int mt = 0; mt < 2; mt++)
                ldm4(a[mt], stg + ((a_base + mt * 2048) ^ kx));
#pragma unroll
            for (int p = 0; p < 2; p++) {
                ldm4(bh[p], stg + 16384 + ((b_base + p * 2048) ^ kx));
                ldm4(bl[p], stg + 32768 + ((b_base + p * 2048) ^ kx));
            }
            // hi product on all 8 accs, then lo product (max ILP between reuses)
#pragma unroll
            for (int mt = 0; mt < 2; mt++)
#pragma unroll
                for (int nt = 0; nt < 4; nt++) {
                    const int p = nt >> 1, q = nt & 1;
                    mma_f16(acc[mt][nt], a[mt], bh[p][q], bh[p][q + 2]);
                }
#pragma unroll
            for (int mt = 0; mt < 2; mt++)
#pragma unroll
                for (int nt = 0; nt < 4; nt++) {
                    const int p = nt >> 1, q = nt & 1;
                    mma_f16(acc[mt][nt], a[mt], bl[p][q], bl[p][q + 2]);
                }
        }
    }

    // ---- epilogue: bias add, float2 stores ----
    const int g  = lane >> 2;
    const int q2 = (lane & 3) * 2;
#pragma unroll
    for (int mt = 0; mt < 2; mt++) {
#pragma unroll
        for (int h = 0; h < 2; h++) {
            const int row = brow + wm * 32 + mt * 16 + g + h * 8;
#pragma unroll
            for (int nt = 0; nt < 4; nt++) {
                const int col = bcol + wn * 32 + nt * 8 + q2;
                float2 v;
                v.x = acc[mt][nt][2 * h + 0] + __ldg(bias + col + 0);
                v.y = acc[mt][nt][2 * h + 1] + __ldg(bias + col + 1);
                *(float2*)(C + (size_t)row * N + col) = v;
            }
        }
    }
}

// ---------------------------------------------------------------------------
// Per-position "head attention" (einsum-label bug replicated exactly).
// Emits fp16 output directly (feeds GEMM2's A operand).
// ---------------------------------------------------------------------------
__global__ __launch_bounds__(256)
void attn_kernel(const float* __restrict__ qkv, __half* __restrict__ oh)
{
    __shared__ __align__(16) float s[3 * Edim];
    __shared__ float en[Hh][Hh + 1];
    __shared__ float rinv[Hh];

    const int bp  = blockIdx.x;
    const int b   = bp >> 11;
    const int pos = bp & 2047;
    const int tid = threadIdx.x;

    {
        const float4* r4 = (const float4*)(qkv + (size_t)bp * 3072);
        float4* s4 = (float4*)s;
#pragma unroll
        for (int t = 0; t < 3; t++) s4[tid + t * 256] = r4[tid + t * 256];
    }
    __syncthreads();

    {
        const int i = tid >> 4;
        const int j = tid & 15;
        const float* q  = s + i * 64;
        const float* kp = s + 1024 + j * 64;
        float e = 0.f;
#pragma unroll
        for (int dd = 0; dd < 16; dd++) {
            const int d4 = ((dd + tid) & 15) * 4;
            float4 qv = *(const float4*)(q + d4);
            float4 kv = *(const float4*)(kp + d4);
            e += qv.x * kv.x + qv.y * kv.y + qv.z * kv.z + qv.w * kv.w;
        }
        en[i][j] = e * 0.03125f;   // 1/sqrt(1024)
    }
    __syncthreads();

    if (tid < Hh) {
        float m = -1e30f;
#pragma unroll
        for (int j = 0; j < Hh; j++) m = fmaxf(m, en[tid][j]);
        float sum = 0.f;
#pragma unroll
        for (int j = 0; j < Hh; j++) {
            const float v = __expf(en[tid][j] - m);
            en[tid][j] = v;
            sum += v;
        }
        rinv[tid] = 1.f / sum;
    }
    __syncthreads();

#pragma unroll
    for (int t0 = 0; t0 < 4; t0++) {
        const int t = tid + t0 * 256;
        const int i = t >> 6;
        const int d = t & 63;
        float o = 0.f;
#pragma unroll
        for (int l = 0; l < Hh; l++)
            o += en[i][l] * s[2048 + l * 64 + d];
        o *= rinv[i];
        const size_t idx = ((size_t)(b * Hh + i) * Nseq + pos) * Dd + d;
        oh[idx] = __float2half_rn(o);
    }
}

// ---------------------------------------------------------------------------
// launch
// ---------------------------------------------------------------------------
extern "C" void kernel_launch(void* const* d_in, const int* in_sizes, int n_in,
                              void* d_out, int out_size)
{
    const float* x    = (const float*)d_in[0];   // [16384,1024]
    const float* Wqkv = (const float*)d_in[1];   // [3072,1024]
    const float* bqkv = (const float*)d_in[2];
    const float* Wo   = (const float*)d_in[3];   // [1024,1024]
    const float* bo   = (const float*)d_in[4];
    float* out = (float*)d_out;

    float* qkv_buf;
    __half *xh, *ath, *wqh, *wql, *woh, *wol;
    cudaGetSymbolAddress((void**)&qkv_buf, g_qkv);
    cudaGetSymbolAddress((void**)&xh,  g_xh);
    cudaGetSymbolAddress((void**)&ath, g_ath);
    cudaGetSymbolAddress((void**)&wqh, g_wqh);
    cudaGetSymbolAddress((void**)&wql, g_wql);
    cudaGetSymbolAddress((void**)&woh, g_woh);
    cudaGetSymbolAddress((void**)&wol, g_wol);

    cudaFuncSetAttribute(gemm_mma, cudaFuncAttributeMaxDynamicSharedMemorySize, GSMEM);

    // 0) x -> fp16; Wqkv, Wo -> fp16 hi/lo splits
    {
        int n4 = Mrows * Edim / 4;
        tohalf_kernel<<<(n4 + 255) / 256, 256>>>((const float4*)x, (uint2*)xh, n4);
        n4 = 3 * Edim * Edim / 4;
        split16_kernel<<<(n4 + 255) / 256, 256>>>((const float4*)Wqkv, (uint2*)wqh, (uint2*)wql, n4);
        n4 = Edim * Edim / 4;
        split16_kernel<<<(n4 + 255) / 256, 256>>>((const float4*)Wo, (uint2*)woh, (uint2*)wol, n4);
    }

    // 1) qkv = x @ Wqkv^T + bqkv   [16384, 3072]
    {
        dim3 grid(3 * Edim / 128, Mrows / 128);
        gemm_mma<<<grid, NTHREADS, GSMEM>>>(xh, wqh, wql, bqkv, qkv_buf, 3 * Edim);
    }

    // 2) per-position head-attention -> fp16 in raw [B,H,N,D] layout
    attn_kernel<<<Mrows, 256>>>(qkv_buf, ath);

    // 3) out = Y @ Wo^T + bo   [16384, 1024]
    {
        dim3 grid(Edim / 128, Mrows / 128);
        gemm_mma<<<grid, NTHREADS, GSMEM>>>(ath, woh, wol, bo, out, Edim);
    }
}

// round 8
// speedup vs baseline: 4.9994x; 1.4862x over previous
#include <cuda_runtime.h>
#include <cuda_fp16.h>
#include <cstdint>

// Problem constants
#define Bdim 8
#define Nseq 2048
#define Edim 1024
#define Hh   16
#define Dd   64
#define Mrows (Bdim * Nseq)      // 16384

// ---------------------------------------------------------------------------
// Scratch (allocation-free rule: __device__ globals)
// ---------------------------------------------------------------------------
__device__ float   g_qkv[(size_t)Mrows * 3 * Edim];   // 192 MB fp32
__device__ __half  g_xh [(size_t)Mrows * Edim];       // x as fp16
__device__ __half  g_ath[(size_t)Mrows * Edim];       // attn out as fp16
__device__ __half  g_wqh[(size_t)3 * Edim * Edim];    // Wqkv fp16
__device__ __half  g_woh[(size_t)Edim * Edim];        // Wo fp16

// ---------------------------------------------------------------------------
// Helpers (baseline-feature PTX only: cp.async, ldmatrix, mma.sync — sm_80+)
// ---------------------------------------------------------------------------
__device__ __forceinline__ uint32_t smem_u32(const void* p) {
    uint32_t a;
    asm("{ .reg .u64 t; cvta.to.shared.u64 t, %1; cvt.u32.u64 %0, t; }" : "=r"(a) : "l"(p));
    return a;
}
#define SWZ(x) ((x) ^ (((x) >> 3) & 0x70))

__device__ __forceinline__ void cp16(uint32_t dst, const void* src) {
    asm volatile("cp.async.cg.shared.global [%0], [%1], 16;" :: "r"(dst), "l"(src));
}
__device__ __forceinline__ void ldm4(uint32_t* r, uint32_t addr) {
    asm volatile("ldmatrix.sync.aligned.m8n8.x4.shared.b16 {%0,%1,%2,%3}, [%4];"
                 : "=r"(r[0]), "=r"(r[1]), "=r"(r[2]), "=r"(r[3]) : "r"(addr));
}
__device__ __forceinline__ void mma_f16(float* c, const uint32_t* a, uint32_t b0, uint32_t b1) {
    asm volatile(
        "mma.sync.aligned.m16n8k16.row.col.f32.f16.f16.f32 "
        "{%0,%1,%2,%3}, {%4,%5,%6,%7}, {%8,%9}, {%0,%1,%2,%3};"
        : "+f"(c[0]), "+f"(c[1]), "+f"(c[2]), "+f"(c[3])
        : "r"(a[0]), "r"(a[1]), "r"(a[2]), "r"(a[3]), "r"(b0), "r"(b1));
}

// ---------------------------------------------------------------------------
// fp32 -> fp16 conversion kernel
// ---------------------------------------------------------------------------
__global__ __launch_bounds__(256)
void tohalf_kernel(const float4* __restrict__ src, uint2* __restrict__ dst, int n4)
{
    int i = blockIdx.x * 256 + threadIdx.x;
    if (i >= n4) return;
    float4 v = src[i];
    __half2 p0 = __floats2half2_rn(v.x, v.y);
    __half2 p1 = __floats2half2_rn(v.z, v.w);
    uint2 u;
    u.x = *(uint32_t*)&p0; u.y = *(uint32_t*)&p1;
    dst[i] = u;
}

// ---------------------------------------------------------------------------
// fp16 NT GEMM via mma.sync: C[M,N] = A[M,K] @ B[N,K]^T + bias[N], fp32 out.
// CTA tile 128x128, BK=64, 3-stage cp.async pipeline, 512 threads (16 warps,
// 4x4, 32x32 per warp). Fragments double-buffered across kk to hide LDSM
// latency. kk advance on a swizzled address is XOR (bits 5-6 are inside the
// swizzle field); mt/p advance (bit 11) is plain add.
// ---------------------------------------------------------------------------
#define STAGES 3
#define STG_BYTES 32768   // A|B, 16KB each
#define GSMEM (STAGES * STG_BYTES + 1024)
#define NTHREADS 512

__global__ __launch_bounds__(NTHREADS, 1)
void gemm_mma(const __half* __restrict__ A, const __half* __restrict__ B,
              const float* __restrict__ bias, float* __restrict__ C, int N)
{
    extern __shared__ char smem_raw[];
    const uint32_t sb = (smem_u32(smem_raw) + 1023) & ~1023u;
    const int tid  = threadIdx.x;
    const int lane = tid & 31;
    const int wid  = tid >> 5;
    const int wm   = wid >> 2;          // 0..3  (M)
    const int wn   = wid & 3;           // 0..3  (N)
    const int brow = blockIdx.y * 128;
    const int bcol = blockIdx.x * 128;

    float acc[2][4][4];
#pragma unroll
    for (int i = 0; i < 2; i++)
#pragma unroll
        for (int j = 0; j < 4; j++)
#pragma unroll
            for (int k = 0; k < 4; k++) acc[i][j][k] = 0.f;

    const int  lrow   = lane & 15;
    const int  lkb    = (lane >> 4) * 16;
    const uint32_t a_base = SWZ((wm * 32 + lrow) * 128 + lkb);
    const uint32_t b_base = SWZ((wn * 32 + lrow) * 128 + lkb);

    // ---- stage loader: 2 tiles x 128 rows x 8 chunks(16B) = 2048 chunks ----
    auto load_stage = [&](int buf, int ks) {
#pragma unroll
        for (int i = 0; i < 4; i++) {
            const int cid  = tid + i * NTHREADS;
            const int tile = cid >> 10;          // 0=A 1=B
            const int r    = (cid >> 3) & 127;
            const int c    = cid & 7;
            const __half* base = tile ? B : A;
            const int row0 = (tile ? bcol : brow) + r;
            cp16(sb + buf * STG_BYTES + tile * 16384 + SWZ(r * 128 + c * 16),
                 base + (size_t)row0 * Edim + ks + c * 8);
        }
        asm volatile("cp.async.commit_group;");
    };

    load_stage(0, 0);
    load_stage(1, 64);
    int fetch = 2;

    uint32_t a[2][2][4], b[2][2][4];   // [buf][mt|p][frag]

    auto load_frags = [&](uint32_t stg, int kk, int buf) {
        const uint32_t kx = kk * 32;
#pragma unroll
        for (int mt = 0; mt < 2; mt++)
            ldm4(a[buf][mt], stg + ((a_base + mt * 2048) ^ kx));
#pragma unroll
        for (int p = 0; p < 2; p++)
            ldm4(b[buf][p], stg + 16384 + ((b_base + p * 2048) ^ kx));
    };

    for (int s = 0; s < 16; ++s) {
        asm volatile("cp.async.wait_group 1;");
        __syncthreads();
        if (fetch < 16) { load_stage(fetch % STAGES, fetch * 64); ++fetch; }
        else            { asm volatile("cp.async.commit_group;"); }

        const uint32_t stg = sb + (s % STAGES) * STG_BYTES;
        load_frags(stg, 0, 0);
#pragma unroll
        for (int kk = 0; kk < 4; kk++) {
            const int cur = kk & 1;
            if (kk < 3) load_frags(stg, kk + 1, cur ^ 1);
#pragma unroll
            for (int mt = 0; mt < 2; mt++)
#pragma unroll
                for (int nt = 0; nt < 4; nt++) {
                    const int p = nt >> 1, q = nt & 1;
                    mma_f16(acc[mt][nt], a[cur][mt], b[cur][p][q], b[cur][p][q + 2]);
                }
        }
    }

    // ---- epilogue: bias add, float2 stores ----
    const int g  = lane >> 2;
    const int q2 = (lane & 3) * 2;
#pragma unroll
    for (int mt = 0; mt < 2; mt++) {
#pragma unroll
        for (int h = 0; h < 2; h++) {
            const int row = brow + wm * 32 + mt * 16 + g + h * 8;
#pragma unroll
            for (int nt = 0; nt < 4; nt++) {
                const int col = bcol + wn * 32 + nt * 8 + q2;
                float2 v;
                v.x = acc[mt][nt][2 * h + 0] + __ldg(bias + col + 0);
                v.y = acc[mt][nt][2 * h + 1] + __ldg(bias + col + 1);
                *(float2*)(C + (size_t)row * N + col) = v;
            }
        }
    }
}

// ---------------------------------------------------------------------------
// Per-position "head attention" (einsum-label bug replicated exactly).
// Emits fp16 output directly (feeds GEMM2's A operand).
// ---------------------------------------------------------------------------
__global__ __launch_bounds__(256)
void attn_kernel(const float* __restrict__ qkv, __half* __restrict__ oh)
{
    __shared__ __align__(16) float s[3 * Edim];
    __shared__ float en[Hh][Hh + 1];
    __shared__ float rinv[Hh];

    const int bp  = blockIdx.x;
    const int b   = bp >> 11;
    const int pos = bp & 2047;
    const int tid = threadIdx.x;

    {
        const float4* r4 = (const float4*)(qkv + (size_t)bp * 3072);
        float4* s4 = (float4*)s;
#pragma unroll
        for (int t = 0; t < 3; t++) s4[tid + t * 256] = r4[tid + t * 256];
    }
    __syncthreads();

    {
        const int i = tid >> 4;
        const int j = tid & 15;
        const float* q  = s + i * 64;
        const float* kp = s + 1024 + j * 64;
        float e = 0.f;
#pragma unroll
        for (int dd = 0; dd < 16; dd++) {
            const int d4 = ((dd + tid) & 15) * 4;
            float4 qv = *(const float4*)(q + d4);
            float4 kv = *(const float4*)(kp + d4);
            e += qv.x * kv.x + qv.y * kv.y + qv.z * kv.z + qv.w * kv.w;
        }
        en[i][j] = e * 0.03125f;   // 1/sqrt(1024)
    }
    __syncthreads();

    if (tid < Hh) {
        float m = -1e30f;
#pragma unroll
        for (int j = 0; j < Hh; j++) m = fmaxf(m, en[tid][j]);
        float sum = 0.f;
#pragma unroll
        for (int j = 0; j < Hh; j++) {
            const float v = __expf(en[tid][j] - m);
            en[tid][j] = v;
            sum += v;
        }
        rinv[tid] = 1.f / sum;
    }
    __syncthreads();

#pragma unroll
    for (int t0 = 0; t0 < 4; t0++) {
        const int t = tid + t0 * 256;
        const int i = t >> 6;
        const int d = t & 63;
        float o = 0.f;
#pragma unroll
        for (int l = 0; l < Hh; l++)
            o += en[i][l] * s[2048 + l * 64 + d];
        o *= rinv[i];
        const size_t idx = ((size_t)(b * Hh + i) * Nseq + pos) * Dd + d;
        oh[idx] = __float2half_rn(o);
    }
}

// ---------------------------------------------------------------------------
// launch
// ---------------------------------------------------------------------------
extern "C" void kernel_launch(void* const* d_in, const int* in_sizes, int n_in,
                              void* d_out, int out_size)
{
    const float* x    = (const float*)d_in[0];   // [16384,1024]
    const float* Wqkv = (const float*)d_in[1];   // [3072,1024]
    const float* bqkv = (const float*)d_in[2];
    const float* Wo   = (const float*)d_in[3];   // [1024,1024]
    const float* bo   = (const float*)d_in[4];
    float* out = (float*)d_out;

    float* qkv_buf;
    __half *xh, *ath, *wqh, *woh;
    cudaGetSymbolAddress((void**)&qkv_buf, g_qkv);
    cudaGetSymbolAddress((void**)&xh,  g_xh);
    cudaGetSymbolAddress((void**)&ath, g_ath);
    cudaGetSymbolAddress((void**)&wqh, g_wqh);
    cudaGetSymbolAddress((void**)&woh, g_woh);

    cudaFuncSetAttribute(gemm_mma, cudaFuncAttributeMaxDynamicSharedMemorySize, GSMEM);

    // 0) x, Wqkv, Wo -> fp16
    {
        int n4 = Mrows * Edim / 4;
        tohalf_kernel<<<(n4 + 255) / 256, 256>>>((const float4*)x, (uint2*)xh, n4);
        n4 = 3 * Edim * Edim / 4;
        tohalf_kernel<<<(n4 + 255) / 256, 256>>>((const float4*)Wqkv, (uint2*)wqh, n4);
        n4 = Edim * Edim / 4;
        tohalf_kernel<<<(n4 + 255) / 256, 256>>>((const float4*)Wo, (uint2*)woh, n4);
    }

    // 1) qkv = x @ Wqkv^T + bqkv   [16384, 3072]
    {
        dim3 grid(3 * Edim / 128, Mrows / 128);
        gemm_mma<<<grid, NTHREADS, GSMEM>>>(xh, wqh, bqkv, qkv_buf, 3 * Edim);
    }

    // 2) per-position head-attention -> fp16 in raw [B,H,N,D] layout
    attn_kernel<<<Mrows, 256>>>(qkv_buf, ath);

    // 3) out = Y @ Wo^T + bo   [16384, 1024]
    {
        dim3 grid(Edim / 128, Mrows / 128);
        gemm_mma<<<grid, NTHREADS, GSMEM>>>(ath, woh, bo, out, Edim);
    }
}

// round 9
// speedup vs baseline: 5.2227x; 1.0447x over previous
#include <cuda_runtime.h>
#include <cuda_fp16.h>
#include <cstdint>

// Problem constants
#define Bdim 8
#define Nseq 2048
#define Edim 1024
#define Hh   16
#define Dd   64
#define Mrows (Bdim * Nseq)      // 16384

// ---------------------------------------------------------------------------
// Scratch (allocation-free rule: __device__ globals)
// ---------------------------------------------------------------------------
__device__ float   g_qkv[(size_t)Mrows * 3 * Edim];   // 192 MB fp32
__device__ __half  g_xh [(size_t)Mrows * Edim];       // x as fp16
__device__ __half  g_ath[(size_t)Mrows * Edim];       // attn out as fp16
__device__ __half  g_wqh[(size_t)3 * Edim * Edim];    // Wqkv fp16
__device__ __half  g_woh[(size_t)Edim * Edim];        // Wo fp16

// ---------------------------------------------------------------------------
// Helpers (baseline-feature PTX only: cp.async, ldmatrix, mma.sync — sm_80+)
// ---------------------------------------------------------------------------
__device__ __forceinline__ uint32_t smem_u32(const void* p) {
    uint32_t a;
    asm("{ .reg .u64 t; cvta.to.shared.u64 t, %1; cvt.u32.u64 %0, t; }" : "=r"(a) : "l"(p));
    return a;
}
#define SWZ(x) ((x) ^ (((x) >> 3) & 0x70))

__device__ __forceinline__ void cp16(uint32_t dst, const void* src) {
    asm volatile("cp.async.cg.shared.global [%0], [%1], 16;" :: "r"(dst), "l"(src));
}
__device__ __forceinline__ void ldm4(uint32_t* r, uint32_t addr) {
    asm volatile("ldmatrix.sync.aligned.m8n8.x4.shared.b16 {%0,%1,%2,%3}, [%4];"
                 : "=r"(r[0]), "=r"(r[1]), "=r"(r[2]), "=r"(r[3]) : "r"(addr));
}
__device__ __forceinline__ void mma_f16(float* c, const uint32_t* a, uint32_t b0, uint32_t b1) {
    asm volatile(
        "mma.sync.aligned.m16n8k16.row.col.f32.f16.f16.f32 "
        "{%0,%1,%2,%3}, {%4,%5,%6,%7}, {%8,%9}, {%0,%1,%2,%3};"
        : "+f"(c[0]), "+f"(c[1]), "+f"(c[2]), "+f"(c[3])
        : "r"(a[0]), "r"(a[1]), "r"(a[2]), "r"(a[3]), "r"(b0), "r"(b1));
}

// ---------------------------------------------------------------------------
// fp32 -> fp16 conversion kernel
// ---------------------------------------------------------------------------
__global__ __launch_bounds__(256)
void tohalf_kernel(const float4* __restrict__ src, uint2* __restrict__ dst, int n4)
{
    int i = blockIdx.x * 256 + threadIdx.x;
    if (i >= n4) return;
    float4 v = src[i];
    __half2 p0 = __floats2half2_rn(v.x, v.y);
    __half2 p1 = __floats2half2_rn(v.z, v.w);
    uint2 u;
    u.x = *(uint32_t*)&p0; u.y = *(uint32_t*)&p1;
    dst[i] = u;
}

// ---------------------------------------------------------------------------
// fp16 NT GEMM via mma.sync: C[M,N] = A[M,K] @ B[N,K]^T + bias[N], fp32 out.
// CTA tile 128x128, K-slab 128 (stored as 4x16KB blocks: Ak0|Ak1|Bk0|Bk1,
// each 128 rows x 128B, SW128-swizzled), 2-stage cp.async pipeline, 512
// threads (16 warps, 4x4, 32x32 per warp). All cp.async src/dst addresses
// hoisted out of the loop (per-slab advance is ptr += 128).
// kk advance on a swizzled address is XOR (bits 5-6 inside swizzle field);
// mt/p advance (bit 11) is plain add; k-half advance is +16KB block.
// ---------------------------------------------------------------------------
#define STG_BYTES 65536   // 4 x 16KB blocks
#define GSMEM (2 * STG_BYTES + 1024)
#define NTHREADS 512

__global__ __launch_bounds__(NTHREADS, 1)
void gemm_mma(const __half* __restrict__ A, const __half* __restrict__ B,
              const float* __restrict__ bias, float* __restrict__ C, int N)
{
    extern __shared__ char smem_raw[];
    const uint32_t sb = (smem_u32(smem_raw) + 1023) & ~1023u;
    const int tid  = threadIdx.x;
    const int lane = tid & 31;
    const int wid  = tid >> 5;
    const int wm   = wid >> 2;          // 0..3  (M)
    const int wn   = wid & 3;           // 0..3  (N)
    const int brow = blockIdx.y * 128;
    const int bcol = blockIdx.x * 128;

    float acc[2][4][4];
#pragma unroll
    for (int i = 0; i < 2; i++)
#pragma unroll
        for (int j = 0; j < 4; j++)
#pragma unroll
            for (int k = 0; k < 4; k++) acc[i][j][k] = 0.f;

    const int  lrow   = lane & 15;
    const int  lkb    = (lane >> 4) * 16;
    const uint32_t a_base = SWZ((wm * 32 + lrow) * 128 + lkb);
    const uint32_t b_base = SWZ((wn * 32 + lrow) * 128 + lkb);

    // ---- hoisted cp.async addressing: 8 chunks/thread/slab ----
    // chunk i: cid = tid + i*512; block = cid>>10 (0=Ak0,1=Ak1,2=Bk0,3=Bk1)
    const __half* gptr[8];
    uint32_t      sdst[8];
#pragma unroll
    for (int i = 0; i < 8; i++) {
        const int cid  = tid + i * NTHREADS;
        const int blk  = cid >> 10;
        const int r    = (cid >> 3) & 127;
        const int c    = cid & 7;
        const __half* base = (blk < 2) ? A : B;
        const int row0 = ((blk < 2) ? brow : bcol) + r;
        gptr[i] = base + (size_t)row0 * Edim + (blk & 1) * 64 + c * 8;
        sdst[i] = sb + blk * 16384 + SWZ(r * 128 + c * 16);
    }

    auto load_stage = [&](uint32_t bufoff) {
#pragma unroll
        for (int i = 0; i < 8; i++) {
            cp16(sdst[i] + bufoff, gptr[i]);
            gptr[i] += 128;
        }
        asm volatile("cp.async.commit_group;");
    };

    load_stage(0);

    uint32_t a[2][2][4], b[2][2][4];   // [frag-buf][mt|p][frag]

    auto load_frags = [&](uint32_t stg, int kk, int buf) {
        const uint32_t blk = (uint32_t)(kk >> 2) * 16384;
        const uint32_t kx  = (uint32_t)(kk & 3) * 32;
#pragma unroll
        for (int mt = 0; mt < 2; mt++)
            ldm4(a[buf][mt], stg + blk + ((a_base + mt * 2048) ^ kx));
#pragma unroll
        for (int p = 0; p < 2; p++)
            ldm4(b[buf][p], stg + 32768 + blk + ((b_base + p * 2048) ^ kx));
    };

    for (int s = 0; s < 8; ++s) {
        asm volatile("cp.async.wait_group 0;");
        __syncthreads();
        if (s < 7) load_stage((uint32_t)((s + 1) & 1) * STG_BYTES);

        const uint32_t stg = sb + (uint32_t)(s & 1) * STG_BYTES;
        load_frags(stg, 0, 0);
#pragma unroll
        for (int kk = 0; kk < 8; kk++) {
            const int cur = kk & 1;
            if (kk < 7) load_frags(stg, kk + 1, cur ^ 1);
#pragma unroll
            for (int mt = 0; mt < 2; mt++)
#pragma unroll
                for (int nt = 0; nt < 4; nt++) {
                    const int p = nt >> 1, q = nt & 1;
                    mma_f16(acc[mt][nt], a[cur][mt], b[cur][p][q], b[cur][p][q + 2]);
                }
        }
    }

    // ---- epilogue: bias add, float2 stores ----
    const int g  = lane >> 2;
    const int q2 = (lane & 3) * 2;
#pragma unroll
    for (int mt = 0; mt < 2; mt++) {
#pragma unroll
        for (int h = 0; h < 2; h++) {
            const int row = brow + wm * 32 + mt * 16 + g + h * 8;
#pragma unroll
            for (int nt = 0; nt < 4; nt++) {
                const int col = bcol + wn * 32 + nt * 8 + q2;
                float2 v;
                v.x = acc[mt][nt][2 * h + 0] + __ldg(bias + col + 0);
                v.y = acc[mt][nt][2 * h + 1] + __ldg(bias + col + 1);
                *(float2*)(C + (size_t)row * N + col) = v;
            }
        }
    }
}

// ---------------------------------------------------------------------------
// Per-position "head attention" (einsum-label bug replicated exactly).
// Emits fp16 output directly (feeds GEMM2's A operand).
// ---------------------------------------------------------------------------
__global__ __launch_bounds__(256)
void attn_kernel(const float* __restrict__ qkv, __half* __restrict__ oh)
{
    __shared__ __align__(16) float s[3 * Edim];
    __shared__ float en[Hh][Hh + 1];
    __shared__ float rinv[Hh];

    const int bp  = blockIdx.x;
    const int b   = bp >> 11;
    const int pos = bp & 2047;
    const int tid = threadIdx.x;

    {
        const float4* r4 = (const float4*)(qkv + (size_t)bp * 3072);
        float4* s4 = (float4*)s;
#pragma unroll
        for (int t = 0; t < 3; t++) s4[tid + t * 256] = r4[tid + t * 256];
    }
    __syncthreads();

    {
        const int i = tid >> 4;
        const int j = tid & 15;
        const float* q  = s + i * 64;
        const float* kp = s + 1024 + j * 64;
        float e = 0.f;
#pragma unroll
        for (int dd = 0; dd < 16; dd++) {
            const int d4 = ((dd + tid) & 15) * 4;
            float4 qv = *(const float4*)(q + d4);
            float4 kv = *(const float4*)(kp + d4);
            e += qv.x * kv.x + qv.y * kv.y + qv.z * kv.z + qv.w * kv.w;
        }
        en[i][j] = e * 0.03125f;   // 1/sqrt(1024)
    }
    __syncthreads();

    if (tid < Hh) {
        float m = -1e30f;
#pragma unroll
        for (int j = 0; j < Hh; j++) m = fmaxf(m, en[tid][j]);
        float sum = 0.f;
#pragma unroll
        for (int j = 0; j < Hh; j++) {
            const float v = __expf(en[tid][j] - m);
            en[tid][j] = v;
            sum += v;
        }
        rinv[tid] = 1.f / sum;
    }
    __syncthreads();

#pragma unroll
    for (int t0 = 0; t0 < 4; t0++) {
        const int t = tid + t0 * 256;
        const int i = t >> 6;
        const int d = t & 63;
        float o = 0.f;
#pragma unroll
        for (int l = 0; l < Hh; l++)
            o += en[i][l] * s[2048 + l * 64 + d];
        o *= rinv[i];
        const size_t idx = ((size_t)(b * Hh + i) * Nseq + pos) * Dd + d;
        oh[idx] = __float2half_rn(o);
    }
}

// ---------------------------------------------------------------------------
// launch
// ---------------------------------------------------------------------------
extern "C" void kernel_launch(void* const* d_in, const int* in_sizes, int n_in,
                              void* d_out, int out_size)
{
    const float* x    = (const float*)d_in[0];   // [16384,1024]
    const float* Wqkv = (const float*)d_in[1];   // [3072,1024]
    const float* bqkv = (const float*)d_in[2];
    const float* Wo   = (const float*)d_in[3];   // [1024,1024]
    const float* bo   = (const float*)d_in[4];
    float* out = (float*)d_out;

    float* qkv_buf;
    __half *xh, *ath, *wqh, *woh;
    cudaGetSymbolAddress((void**)&qkv_buf, g_qkv);
    cudaGetSymbolAddress((void**)&xh,  g_xh);
    cudaGetSymbolAddress((void**)&ath, g_ath);
    cudaGetSymbolAddress((void**)&wqh, g_wqh);
    cudaGetSymbolAddress((void**)&woh, g_woh);

    cudaFuncSetAttribute(gemm_mma, cudaFuncAttributeMaxDynamicSharedMemorySize, GSMEM);

    // 0) x, Wqkv, Wo -> fp16
    {
        int n4 = Mrows * Edim / 4;
        tohalf_kernel<<<(n4 + 255) / 256, 256>>>((const float4*)x, (uint2*)xh, n4);
        n4 = 3 * Edim * Edim / 4;
        tohalf_kernel<<<(n4 + 255) / 256, 256>>>((const float4*)Wqkv, (uint2*)wqh, n4);
        n4 = Edim * Edim / 4;
        tohalf_kernel<<<(n4 + 255) / 256, 256>>>((const float4*)Wo, (uint2*)woh, n4);
    }

    // 1) qkv = x @ Wqkv^T + bqkv   [16384, 3072]
    {
        dim3 grid(3 * Edim / 128, Mrows / 128);
        gemm_mma<<<grid, NTHREADS, GSMEM>>>(xh, wqh, bqkv, qkv_buf, 3 * Edim);
    }

    // 2) per-position head-attention -> fp16 in raw [B,H,N,D] layout
    attn_kernel<<<Mrows, 256>>>(qkv_buf, ath);

    // 3) out = Y @ Wo^T + bo   [16384, 1024]
    {
        dim3 grid(Edim / 128, Mrows / 128);
        gemm_mma<<<grid, NTHREADS, GSMEM>>>(ath, woh, bo, out, Edim);
    }
}

// round 10
// speedup vs baseline: 5.2789x; 1.0108x over previous
#include <cuda_runtime.h>
#include <cuda_fp16.h>
#include <cstdint>

// Problem constants
#define Bdim 8
#define Nseq 2048
#define Edim 1024
#define Hh   16
#define Dd   64
#define Mrows (Bdim * Nseq)      // 16384

// ---------------------------------------------------------------------------
// Scratch (allocation-free rule: __device__ globals)
// ---------------------------------------------------------------------------
__device__ float   g_qkv[(size_t)Mrows * 3 * Edim];   // 192 MB fp32
__device__ __half  g_xh [(size_t)Mrows * Edim];       // x as fp16
__device__ __half  g_ath[(size_t)Mrows * Edim];       // attn out as fp16
__device__ __half  g_wqh[(size_t)3 * Edim * Edim];    // Wqkv fp16
__device__ __half  g_woh[(size_t)Edim * Edim];        // Wo fp16

// ---------------------------------------------------------------------------
// Helpers (baseline-feature PTX only: cp.async, ldmatrix, mma.sync — sm_80+)
// ---------------------------------------------------------------------------
__device__ __forceinline__ uint32_t smem_u32(const void* p) {
    uint32_t a;
    asm("{ .reg .u64 t; cvta.to.shared.u64 t, %1; cvt.u32.u64 %0, t; }" : "=r"(a) : "l"(p));
    return a;
}
#define SWZ(x) ((x) ^ (((x) >> 3) & 0x70))

__device__ __forceinline__ void cp16(uint32_t dst, const void* src) {
    asm volatile("cp.async.cg.shared.global [%0], [%1], 16;" :: "r"(dst), "l"(src));
}
__device__ __forceinline__ void ldm4(uint32_t* r, uint32_t addr) {
    asm volatile("ldmatrix.sync.aligned.m8n8.x4.shared.b16 {%0,%1,%2,%3}, [%4];"
                 : "=r"(r[0]), "=r"(r[1]), "=r"(r[2]), "=r"(r[3]) : "r"(addr));
}
__device__ __forceinline__ void mma_f16(float* c, const uint32_t* a, uint32_t b0, uint32_t b1) {
    asm volatile(
        "mma.sync.aligned.m16n8k16.row.col.f32.f16.f16.f32 "
        "{%0,%1,%2,%3}, {%4,%5,%6,%7}, {%8,%9}, {%0,%1,%2,%3};"
        : "+f"(c[0]), "+f"(c[1]), "+f"(c[2]), "+f"(c[3])
        : "r"(a[0]), "r"(a[1]), "r"(a[2]), "r"(a[3]), "r"(b0), "r"(b1));
}

// ---------------------------------------------------------------------------
// fp32 -> fp16 conversion kernel
// ---------------------------------------------------------------------------
__global__ __launch_bounds__(256)
void tohalf_kernel(const float4* __restrict__ src, uint2* __restrict__ dst, int n4)
{
    int i = blockIdx.x * 256 + threadIdx.x;
    if (i >= n4) return;
    float4 v = src[i];
    __half2 p0 = __floats2half2_rn(v.x, v.y);
    __half2 p1 = __floats2half2_rn(v.z, v.w);
    uint2 u;
    u.x = *(uint32_t*)&p0; u.y = *(uint32_t*)&p1;
    dst[i] = u;
}

// ---------------------------------------------------------------------------
// fp16 NT GEMM via mma.sync: C[M,N] = A[M,K] @ B[N,K]^T + bias[N], fp32 out.
// CTA tile 128x256, K-slab 128. SMEM stage layout (96KB):
//   [0,16K)   A k-half0 (128r x 128B, SW128)
//   [16K,32K) A k-half1
//   [32K,64K) B k-half0 (256r x 128B)
//   [64K,96K) B k-half1
// 2-stage cp.async pipeline, 512 threads (16 warps, 4x4, 32x64 per warp).
// Per kk: 6 ldm4 (2 A + 4 B) feed 16 HMMA -> 25% less smem read per FLOP
// than 32x32 warp tiles. kk advance on swizzled addr is XOR (bits 5-6).
// ---------------------------------------------------------------------------
#define STG_BYTES 98304   // 32KB A + 64KB B
#define GSMEM (2 * STG_BYTES + 1024)
#define NTHREADS 512

__global__ __launch_bounds__(NTHREADS, 1)
void gemm_mma(const __half* __restrict__ A, const __half* __restrict__ B,
              const float* __restrict__ bias, float* __restrict__ C, int N)
{
    extern __shared__ char smem_raw[];
    const uint32_t sb = (smem_u32(smem_raw) + 1023) & ~1023u;
    const int tid  = threadIdx.x;
    const int lane = tid & 31;
    const int wid  = tid >> 5;
    const int wm   = wid >> 2;          // 0..3  (M, 32 rows each)
    const int wn   = wid & 3;           // 0..3  (N, 64 cols each)
    const int brow = blockIdx.y * 128;
    const int bcol = blockIdx.x * 256;

    float acc[2][8][4];
#pragma unroll
    for (int i = 0; i < 2; i++)
#pragma unroll
        for (int j = 0; j < 8; j++)
#pragma unroll
            for (int k = 0; k < 4; k++) acc[i][j][k] = 0.f;

    const int  lrow   = lane & 15;
    const int  lkb    = (lane >> 4) * 16;
    const uint32_t a_base = SWZ((wm * 32 + lrow) * 128 + lkb);
    const uint32_t b_base = SWZ((wn * 64 + lrow) * 128 + lkb);

    // ---- hoisted cp.async addressing: 12 chunks/thread/slab ----
    // cid 0..2047: A (2 k-half blocks of 1024); cid 2048..6143: B (2 blocks of 2048)
    const __half* gptr[12];
    uint32_t      sdst[12];
#pragma unroll
    for (int i = 0; i < 12; i++) {
        const int cid = tid + i * NTHREADS;
        if (cid < 2048) {
            const int kh = cid >> 10;
            const int r  = (cid >> 3) & 127;
            const int c  = cid & 7;
            gptr[i] = A + (size_t)(brow + r) * Edim + kh * 64 + c * 8;
            sdst[i] = sb + kh * 16384 + SWZ(r * 128 + c * 16);
        } else {
            const int cb = cid - 2048;
            const int kh = cb >> 11;
            const int r  = (cb >> 3) & 255;
            const int c  = cb & 7;
            gptr[i] = B + (size_t)(bcol + r) * Edim + kh * 64 + c * 8;
            sdst[i] = sb + 32768 + kh * 32768 + SWZ(r * 128 + c * 16);
        }
    }

    auto load_stage = [&](uint32_t bufoff) {
#pragma unroll
        for (int i = 0; i < 12; i++) {
            cp16(sdst[i] + bufoff, gptr[i]);
            gptr[i] += 128;
        }
        asm volatile("cp.async.commit_group;");
    };

    load_stage(0);

    for (int s = 0; s < 8; ++s) {
        asm volatile("cp.async.wait_group 0;");
        __syncthreads();
        if (s < 7) load_stage((uint32_t)((s + 1) & 1) * STG_BYTES);

        const uint32_t stg = sb + (uint32_t)(s & 1) * STG_BYTES;
#pragma unroll
        for (int kk = 0; kk < 8; kk++) {
            const uint32_t kx   = (uint32_t)(kk & 3) * 32;
            const uint32_t ablk = stg + (uint32_t)(kk >> 2) * 16384;
            const uint32_t bblk = stg + 32768 + (uint32_t)(kk >> 2) * 32768;
            uint32_t a[2][4], b[4][4];
#pragma unroll
            for (int mt = 0; mt < 2; mt++)
                ldm4(a[mt], ablk + ((a_base + mt * 2048) ^ kx));
#pragma unroll
            for (int p = 0; p < 4; p++)
                ldm4(b[p], bblk + ((b_base + p * 2048) ^ kx));
#pragma unroll
            for (int mt = 0; mt < 2; mt++)
#pragma unroll
                for (int nt = 0; nt < 8; nt++) {
                    const int p = nt >> 1, q = nt & 1;
                    mma_f16(acc[mt][nt], a[mt], b[p][q], b[p][q + 2]);
                }
        }
    }

    // ---- epilogue: bias add, float2 stores ----
    const int g  = lane >> 2;
    const int q2 = (lane & 3) * 2;
#pragma unroll
    for (int mt = 0; mt < 2; mt++) {
#pragma unroll
        for (int h = 0; h < 2; h++) {
            const int row = brow + wm * 32 + mt * 16 + g + h * 8;
#pragma unroll
            for (int nt = 0; nt < 8; nt++) {
                const int col = bcol + wn * 64 + nt * 8 + q2;
                float2 v;
                v.x = acc[mt][nt][2 * h + 0] + __ldg(bias + col + 0);
                v.y = acc[mt][nt][2 * h + 1] + __ldg(bias + col + 1);
                *(float2*)(C + (size_t)row * N + col) = v;
            }
        }
    }
}

// ---------------------------------------------------------------------------
// Per-position "head attention" (einsum-label bug replicated exactly).
// Emits fp16 output directly (feeds GEMM2's A operand).
// ---------------------------------------------------------------------------
__global__ __launch_bounds__(256)
void attn_kernel(const float* __restrict__ qkv, __half* __restrict__ oh)
{
    __shared__ __align__(16) float s[3 * Edim];
    __shared__ float en[Hh][Hh + 1];
    __shared__ float rinv[Hh];

    const int bp  = blockIdx.x;
    const int b   = bp >> 11;
    const int pos = bp & 2047;
    const int tid = threadIdx.x;

    {
        const float4* r4 = (const float4*)(qkv + (size_t)bp * 3072);
        float4* s4 = (float4*)s;
#pragma unroll
        for (int t = 0; t < 3; t++) s4[tid + t * 256] = r4[tid + t * 256];
    }
    __syncthreads();

    {
        const int i = tid >> 4;
        const int j = tid & 15;
        const float* q  = s + i * 64;
        const float* kp = s + 1024 + j * 64;
        float e = 0.f;
#pragma unroll
        for (int dd = 0; dd < 16; dd++) {
            const int d4 = ((dd + tid) & 15) * 4;
            float4 qv = *(const float4*)(q + d4);
            float4 kv = *(const float4*)(kp + d4);
            e += qv.x * kv.x + qv.y * kv.y + qv.z * kv.z + qv.w * kv.w;
        }
        en[i][j] = e * 0.03125f;   // 1/sqrt(1024)
    }
    __syncthreads();

    if (tid < Hh) {
        float m = -1e30f;
#pragma unroll
        for (int j = 0; j < Hh; j++) m = fmaxf(m, en[tid][j]);
        float sum = 0.f;
#pragma unroll
        for (int j = 0; j < Hh; j++) {
            const float v = __expf(en[tid][j] - m);
            en[tid][j] = v;
            sum += v;
        }
        rinv[tid] = 1.f / sum;
    }
    __syncthreads();

#pragma unroll
    for (int t0 = 0; t0 < 4; t0++) {
        const int t = tid + t0 * 256;
        const int i = t >> 6;
        const int d = t & 63;
        float o = 0.f;
#pragma unroll
        for (int l = 0; l < Hh; l++)
            o += en[i][l] * s[2048 + l * 64 + d];
        o *= rinv[i];
        const size_t idx = ((size_t)(b * Hh + i) * Nseq + pos) * Dd + d;
        oh[idx] = __float2half_rn(o);
    }
}

// ---------------------------------------------------------------------------
// launch
// ---------------------------------------------------------------------------
extern "C" void kernel_launch(void* const* d_in, const int* in_sizes, int n_in,
                              void* d_out, int out_size)
{
    const float* x    = (const float*)d_in[0];   // [16384,1024]
    const float* Wqkv = (const float*)d_in[1];   // [3072,1024]
    const float* bqkv = (const float*)d_in[2];
    const float* Wo   = (const float*)d_in[3];   // [1024,1024]
    const float* bo   = (const float*)d_in[4];
    float* out = (float*)d_out;

    float* qkv_buf;
    __half *xh, *ath, *wqh, *woh;
    cudaGetSymbolAddress((void**)&qkv_buf, g_qkv);
    cudaGetSymbolAddress((void**)&xh,  g_xh);
    cudaGetSymbolAddress((void**)&ath, g_ath);
    cudaGetSymbolAddress((void**)&wqh, g_wqh);
    cudaGetSymbolAddress((void**)&woh, g_woh);

    cudaFuncSetAttribute(gemm_mma, cudaFuncAttributeMaxDynamicSharedMemorySize, GSMEM);

    // 0) x, Wqkv, Wo -> fp16
    {
        int n4 = Mrows * Edim / 4;
        tohalf_kernel<<<(n4 + 255) / 256, 256>>>((const float4*)x, (uint2*)xh, n4);
        n4 = 3 * Edim * Edim / 4;
        tohalf_kernel<<<(n4 + 255) / 256, 256>>>((const float4*)Wqkv, (uint2*)wqh, n4);
        n4 = Edim * Edim / 4;
        tohalf_kernel<<<(n4 + 255) / 256, 256>>>((const float4*)Wo, (uint2*)woh, n4);
    }

    // 1) qkv = x @ Wqkv^T + bqkv   [16384, 3072]
    {
        dim3 grid(3 * Edim / 256, Mrows / 128);
        gemm_mma<<<grid, NTHREADS, GSMEM>>>(xh, wqh, bqkv, qkv_buf, 3 * Edim);
    }

    // 2) per-position head-attention -> fp16 in raw [B,H,N,D] layout
    attn_kernel<<<Mrows, 256>>>(qkv_buf, ath);

    // 3) out = Y @ Wo^T + bo   [16384, 1024]
    {
        dim3 grid(Edim / 256, Mrows / 128);
        gemm_mma<<<grid, NTHREADS, GSMEM>>>(ath, woh, bo, out, Edim);
    }
}

// round 11
// speedup vs baseline: 5.4537x; 1.0331x over previous
#include <cuda_runtime.h>
#include <cuda_fp16.h>
#include <cstdint>

// Problem constants
#define Bdim 8
#define Nseq 2048
#define Edim 1024
#define Hh   16
#define Dd   64
#define Mrows (Bdim * Nseq)      // 16384

// ---------------------------------------------------------------------------
// Scratch (allocation-free rule: __device__ globals)
// ---------------------------------------------------------------------------
__device__ float   g_qkv[(size_t)Mrows * 3 * Edim];   // 192 MB fp32
__device__ __half  g_xh [(size_t)Mrows * Edim];       // x as fp16
__device__ __half  g_ath[(size_t)Mrows * Edim];       // attn out as fp16
__device__ __half  g_wqh[(size_t)3 * Edim * Edim];    // Wqkv fp16
__device__ __half  g_woh[(size_t)Edim * Edim];        // Wo fp16

// ---------------------------------------------------------------------------
// Helpers (baseline-feature PTX only: cp.async, ldmatrix, mma.sync — sm_80+)
// ---------------------------------------------------------------------------
__device__ __forceinline__ uint32_t smem_u32(const void* p) {
    uint32_t a;
    asm("{ .reg .u64 t; cvta.to.shared.u64 t, %1; cvt.u32.u64 %0, t; }" : "=r"(a) : "l"(p));
    return a;
}
#define SWZ(x) ((x) ^ (((x) >> 3) & 0x70))

__device__ __forceinline__ void cp16(uint32_t dst, const void* src) {
    asm volatile("cp.async.cg.shared.global [%0], [%1], 16;" :: "r"(dst), "l"(src));
}
__device__ __forceinline__ void ldm4(uint32_t* r, uint32_t addr) {
    asm volatile("ldmatrix.sync.aligned.m8n8.x4.shared.b16 {%0,%1,%2,%3}, [%4];"
                 : "=r"(r[0]), "=r"(r[1]), "=r"(r[2]), "=r"(r[3]) : "r"(addr));
}
__device__ __forceinline__ void mma_f16(float* c, const uint32_t* a, uint32_t b0, uint32_t b1) {
    asm volatile(
        "mma.sync.aligned.m16n8k16.row.col.f32.f16.f16.f32 "
        "{%0,%1,%2,%3}, {%4,%5,%6,%7}, {%8,%9}, {%0,%1,%2,%3};"
        : "+f"(c[0]), "+f"(c[1]), "+f"(c[2]), "+f"(c[3])
        : "r"(a[0]), "r"(a[1]), "r"(a[2]), "r"(a[3]), "r"(b0), "r"(b1));
}

// ---------------------------------------------------------------------------
// fp32 -> fp16 conversion kernel
// ---------------------------------------------------------------------------
__global__ __launch_bounds__(256)
void tohalf_kernel(const float4* __restrict__ src, uint2* __restrict__ dst, int n4)
{
    int i = blockIdx.x * 256 + threadIdx.x;
    if (i >= n4) return;
    float4 v = src[i];
    __half2 p0 = __floats2half2_rn(v.x, v.y);
    __half2 p1 = __floats2half2_rn(v.z, v.w);
    uint2 u;
    u.x = *(uint32_t*)&p0; u.y = *(uint32_t*)&p1;
    dst[i] = u;
}

// ---------------------------------------------------------------------------
// fp16 NT GEMM via mma.sync: C[M,N] = A[M,K] @ B[N,K]^T + bias[N], fp32 out.
// CTA tile 128x256, K-slab 128. SMEM stage (96KB):
//   [0,16K) A kh0 | [16K,32K) A kh1 | [32K,64K) B kh0 | [64K,96K) B kh1
// (all 128B rows, SW128-swizzled). 2-stage cp.async pipeline, 512 threads
// (16 warps 4x4, 32x64 per warp).
// Addressing state is 2 pointers + 2 smem bases; all 12 chunk offsets are
// compile-time constants (chunks step by +64 rows / +k-half, and +8192B in
// smem is above the swizzle field so plain add is safe).
// ---------------------------------------------------------------------------
#define STG_BYTES 98304   // 32KB A + 64KB B
#define GSMEM (2 * STG_BYTES + 1024)
#define NTHREADS 512

__global__ __launch_bounds__(NTHREADS, 1)
void gemm_mma(const __half* __restrict__ A, const __half* __restrict__ B,
              const float* __restrict__ bias, float* __restrict__ C, int N)
{
    extern __shared__ char smem_raw[];
    const uint32_t sb = (smem_u32(smem_raw) + 1023) & ~1023u;
    const int tid  = threadIdx.x;
    const int lane = tid & 31;
    const int wid  = tid >> 5;
    const int wm   = wid >> 2;          // 0..3  (M, 32 rows)
    const int wn   = wid & 3;           // 0..3  (N, 64 cols)
    const int brow = blockIdx.y * 128;
    const int bcol = blockIdx.x * 256;

    float acc[2][8][4];
#pragma unroll
    for (int i = 0; i < 2; i++)
#pragma unroll
        for (int j = 0; j < 8; j++)
#pragma unroll
            for (int k = 0; k < 4; k++) acc[i][j][k] = 0.f;

    const int  lrow   = lane & 15;
    const int  lkb    = (lane >> 4) * 16;
    const uint32_t a_base = SWZ((wm * 32 + lrow) * 128 + lkb);
    const uint32_t b_base = SWZ((wn * 64 + lrow) * 128 + lkb);

    // ---- minimal-state cp.async addressing ----
    // Per thread: row r0 = tid>>3 (0..63), 16B-chunk c = tid&7.
    // A chunks (4): (kh,rowoff) in {0,1} x {0,64};  B chunks (8): kh x {0,64,128,192}.
    const int r0 = tid >> 3;
    const int c8 = (tid & 7) * 8;     // element offset of 16B chunk
    const __half* aptr = A + (size_t)(brow + r0) * Edim + c8;
    const __half* bptr = B + (size_t)(bcol + r0) * Edim + c8;
    const uint32_t saw = SWZ(r0 * 128 + (tid & 7) * 16);
    const uint32_t sa0 = sb + saw;            // A kh0 block base
    const uint32_t sb0 = sb + 32768 + saw;    // B kh0 block base

    auto load_stage = [&](uint32_t bo) {
        // A: kh0 rows r0, r0+64; kh1 rows r0, r0+64
        cp16(sa0 + bo,                 aptr);
        cp16(sa0 + bo + 8192,          aptr + 64 * Edim);
        cp16(sa0 + bo + 16384,         aptr + 64);
        cp16(sa0 + bo + 16384 + 8192,  aptr + 64 * Edim + 64);
        // B: kh0 rows r0..r0+192; kh1 same
#pragma unroll
        for (int j = 0; j < 4; j++) {
            cp16(sb0 + bo + j * 8192,          bptr + j * 64 * Edim);
            cp16(sb0 + bo + 32768 + j * 8192,  bptr + j * 64 * Edim + 64);
        }
        asm volatile("cp.async.commit_group;");
        aptr += 128;
        bptr += 128;
    };

    load_stage(0);

    for (int s = 0; s < 8; ++s) {
        asm volatile("cp.async.wait_group 0;");
        __syncthreads();
        if (s < 7) load_stage((uint32_t)((s + 1) & 1) * STG_BYTES);

        const uint32_t stg = sb + (uint32_t)(s & 1) * STG_BYTES;
#pragma unroll
        for (int kk = 0; kk < 8; kk++) {
            const uint32_t kx   = (uint32_t)(kk & 3) * 32;
            const uint32_t ablk = stg + (uint32_t)(kk >> 2) * 16384;
            const uint32_t bblk = stg + 32768 + (uint32_t)(kk >> 2) * 32768;
            uint32_t a[2][4], b[4][4];
#pragma unroll
            for (int mt = 0; mt < 2; mt++)
                ldm4(a[mt], ablk + ((a_base + mt * 2048) ^ kx));
#pragma unroll
            for (int p = 0; p < 4; p++)
                ldm4(b[p], bblk + ((b_base + p * 2048) ^ kx));
#pragma unroll
            for (int mt = 0; mt < 2; mt++)
#pragma unroll
                for (int nt = 0; nt < 8; nt++) {
                    const int p = nt >> 1, q = nt & 1;
                    mma_f16(acc[mt][nt], a[mt], b[p][q], b[p][q + 2]);
                }
        }
    }

    // ---- epilogue: bias add, float2 stores ----
    const int g  = lane >> 2;
    const int q2 = (lane & 3) * 2;
#pragma unroll
    for (int mt = 0; mt < 2; mt++) {
#pragma unroll
        for (int h = 0; h < 2; h++) {
            const int row = brow + wm * 32 + mt * 16 + g + h * 8;
#pragma unroll
            for (int nt = 0; nt < 8; nt++) {
                const int col = bcol + wn * 64 + nt * 8 + q2;
                float2 v;
                v.x = acc[mt][nt][2 * h + 0] + __ldg(bias + col + 0);
                v.y = acc[mt][nt][2 * h + 1] + __ldg(bias + col + 1);
                *(float2*)(C + (size_t)row * N + col) = v;
            }
        }
    }
}

// ---------------------------------------------------------------------------
// Per-position "head attention" (einsum-label bug replicated exactly).
// Emits fp16 output directly (feeds GEMM2's A operand).
// ---------------------------------------------------------------------------
__global__ __launch_bounds__(256)
void attn_kernel(const float* __restrict__ qkv, __half* __restrict__ oh)
{
    __shared__ __align__(16) float s[3 * Edim];
    __shared__ float en[Hh][Hh + 1];
    __shared__ float rinv[Hh];

    const int bp  = blockIdx.x;
    const int b   = bp >> 11;
    const int pos = bp & 2047;
    const int tid = threadIdx.x;

    {
        const float4* r4 = (const float4*)(qkv + (size_t)bp * 3072);
        float4* s4 = (float4*)s;
#pragma unroll
        for (int t = 0; t < 3; t++) s4[tid + t * 256] = r4[tid + t * 256];
    }
    __syncthreads();

    {
        const int i = tid >> 4;
        const int j = tid & 15;
        const float* q  = s + i * 64;
        const float* kp = s + 1024 + j * 64;
        float e = 0.f;
#pragma unroll
        for (int dd = 0; dd < 16; dd++) {
            const int d4 = ((dd + tid) & 15) * 4;
            float4 qv = *(const float4*)(q + d4);
            float4 kv = *(const float4*)(kp + d4);
            e += qv.x * kv.x + qv.y * kv.y + qv.z * kv.z + qv.w * kv.w;
        }
        en[i][j] = e * 0.03125f;   // 1/sqrt(1024)
    }
    __syncthreads();

    if (tid < Hh) {
        float m = -1e30f;
#pragma unroll
        for (int j = 0; j < Hh; j++) m = fmaxf(m, en[tid][j]);
        float sum = 0.f;
#pragma unroll
        for (int j = 0; j < Hh; j++) {
            const float v = __expf(en[tid][j] - m);
            en[tid][j] = v;
            sum += v;
        }
        rinv[tid] = 1.f / sum;
    }
    __syncthreads();

#pragma unroll
    for (int t0 = 0; t0 < 4; t0++) {
        const int t = tid + t0 * 256;
        const int i = t >> 6;
        const int d = t & 63;
        float o = 0.f;
#pragma unroll
        for (int l = 0; l < Hh; l++)
            o += en[i][l] * s[2048 + l * 64 + d];
        o *= rinv[i];
        const size_t idx = ((size_t)(b * Hh + i) * Nseq + pos) * Dd + d;
        oh[idx] = __float2half_rn(o);
    }
}

// ---------------------------------------------------------------------------
// launch
// ---------------------------------------------------------------------------
extern "C" void kernel_launch(void* const* d_in, const int* in_sizes, int n_in,
                              void* d_out, int out_size)
{
    const float* x    = (const float*)d_in[0];   // [16384,1024]
    const float* Wqkv = (const float*)d_in[1];   // [3072,1024]
    const float* bqkv = (const float*)d_in[2];
    const float* Wo   = (const float*)d_in[3];   // [1024,1024]
    const float* bo   = (const float*)d_in[4];
    float* out = (float*)d_out;

    float* qkv_buf;
    __half *xh, *ath, *wqh, *woh;
    cudaGetSymbolAddress((void**)&qkv_buf, g_qkv);
    cudaGetSymbolAddress((void**)&xh,  g_xh);
    cudaGetSymbolAddress((void**)&ath, g_ath);
    cudaGetSymbolAddress((void**)&wqh, g_wqh);
    cudaGetSymbolAddress((void**)&woh, g_woh);

    cudaFuncSetAttribute(gemm_mma, cudaFuncAttributeMaxDynamicSharedMemorySize, GSMEM);

    // 0) x, Wqkv, Wo -> fp16
    {
        int n4 = Mrows * Edim / 4;
        tohalf_kernel<<<(n4 + 255) / 256, 256>>>((const float4*)x, (uint2*)xh, n4);
        n4 = 3 * Edim * Edim / 4;
        tohalf_kernel<<<(n4 + 255) / 256, 256>>>((const float4*)Wqkv, (uint2*)wqh, n4);
        n4 = Edim * Edim / 4;
        tohalf_kernel<<<(n4 + 255) / 256, 256>>>((const float4*)Wo, (uint2*)woh, n4);
    }

    // 1) qkv = x @ Wqkv^T + bqkv   [16384, 3072]
    {
        dim3 grid(3 * Edim / 256, Mrows / 128);
        gemm_mma<<<grid, NTHREADS, GSMEM>>>(xh, wqh, bqkv, qkv_buf, 3 * Edim);
    }

    // 2) per-position head-attention -> fp16 in raw [B,H,N,D] layout
    attn_kernel<<<Mrows, 256>>>(qkv_buf, ath);

    // 3) out = Y @ Wo^T + bo   [16384, 1024]
    {
        dim3 grid(Edim / 256, Mrows / 128);
        gemm_mma<<<grid, NTHREADS, GSMEM>>>(ath, woh, bo, out, Edim);
    }
}